// round 3
// baseline (speedup 1.0000x reference)
#include <cuda_runtime.h>
#include <cstdint>

// Problem constants (fixed by the dataset)
#define BB_  8
#define TT_  2048
#define DD_  1024
#define MM_  (BB_ * TT_)   // 16384

// ---------------------------------------------------------------------------
// Scratch (no cudaMalloc allowed): 4 x 64MB fp32 buffers + small dump area
// ---------------------------------------------------------------------------
__device__ float g_k[MM_ * DD_];
__device__ float g_v[MM_ * DD_];
__device__ float g_r[MM_ * DD_];
__device__ float g_rwkv[MM_ * DD_];
__device__ float g_dump[4 * BB_ * DD_];   // fallback if harness out lacks state slots

// ---------------------------------------------------------------------------
// Packed f32x2 helpers (SASS FFMA2: 2x fp32 FMA throughput on sm_103a)
// ---------------------------------------------------------------------------
__device__ __forceinline__ unsigned long long pack_dup(float a) {
    unsigned long long r;
    asm("mov.b64 %0, {%1, %1};" : "=l"(r) : "f"(a));
    return r;
}
__device__ __forceinline__ void ffma2(unsigned long long& c,
                                      unsigned long long a,
                                      unsigned long long b) {
    asm("fma.rn.f32x2 %0, %1, %2, %0;" : "+l"(c) : "l"(a), "l"(b));
}
__device__ __forceinline__ float2 unpack2(unsigned long long c) {
    float2 f;
    asm("mov.b64 {%0, %1}, %2;" : "=f"(f.x), "=f"(f.y) : "l"(c));
    return f;
}

__device__ __forceinline__ float sigmoidf_(float x) {
    return 1.0f / (1.0f + __expf(-x));
}

// ---------------------------------------------------------------------------
// SGEMM: C[M=16384, N=1024] = A[M, K=1024] * W[K, N]
//   MIX: A is built on the fly as  x*tm + xshift*(1-tm)  (token shift)
//   SIG: apply sigmoid to C (for the r projection)
// Tiling: BM=BN=128, BK=16, 256 threads, 8x8 microtile, FFMA2 inner loop.
// ---------------------------------------------------------------------------
template <bool MIX, bool SIG>
__global__ void __launch_bounds__(256, 2)
gemm128(const float* __restrict__ A,      // x (MIX) or rwkv (plain)
        const float* __restrict__ lastx,  // [B, D] (MIX only)
        const float* __restrict__ tmix,   // [D]    (MIX only)
        const float* __restrict__ W,      // [K, N] row-major, N = D
        float* __restrict__ Cout)         // [M, N]
{
    constexpr int BM = 128, BN = 128, BK = 16;
    constexpr int LDA = BM + 4;   // 132: keeps float4 rows 16B-aligned (528B stride)
    constexpr int LDB = BN + 4;

    __shared__ __align__(16) float As[BK][LDA];   // transposed: As[k][m]
    __shared__ __align__(16) float Bs[BK][LDB];   // Bs[k][n]

    const int bn0 = blockIdx.x * BN;
    const int bm0 = blockIdx.y * BM;
    const int tid = threadIdx.x;
    const int tcol = tid & 15;   // 0..15 -> 8 output cols each
    const int trow = tid >> 4;   // 0..15 -> 8 output rows each

    unsigned long long acc[8][4];
#pragma unroll
    for (int i = 0; i < 8; i++)
#pragma unroll
        for (int j = 0; j < 4; j++) acc[i][j] = 0ull;

    for (int k0 = 0; k0 < DD_; k0 += BK) {
        // ---- load A tile (with fused token-shift mix) ----
#pragma unroll
        for (int i = 0; i < 2; i++) {
            int f = i * 256 + tid;          // 0..511 float4s
            int ar = f >> 2;                // row 0..127
            int ac = (f & 3) * 4;           // col 0,4,8,12
            int m = bm0 + ar;
            const float4 xv = *(const float4*)(A + (size_t)m * DD_ + k0 + ac);
            float4 av;
            if (MIX) {
                float4 xp;
                if ((m & (TT_ - 1)) == 0) {           // t == 0 -> last_x
                    int b = m >> 11;                  // m / T
                    xp = *(const float4*)(lastx + b * DD_ + k0 + ac);
                } else {
                    xp = *(const float4*)(A + (size_t)(m - 1) * DD_ + k0 + ac);
                }
                const float4 tm = *(const float4*)(tmix + k0 + ac);
                av.x = fmaf(tm.x, xv.x - xp.x, xp.x);
                av.y = fmaf(tm.y, xv.y - xp.y, xp.y);
                av.z = fmaf(tm.z, xv.z - xp.z, xp.z);
                av.w = fmaf(tm.w, xv.w - xp.w, xp.w);
            } else {
                av = xv;
            }
            As[ac + 0][ar] = av.x;
            As[ac + 1][ar] = av.y;
            As[ac + 2][ar] = av.z;
            As[ac + 3][ar] = av.w;
        }
        // ---- load B tile (16 x 128, fully coalesced) ----
#pragma unroll
        for (int i = 0; i < 2; i++) {
            int f = i * 256 + tid;
            int br = f >> 5;                // 0..15
            int bc = (f & 31) * 4;          // 0..124
            *(float4*)&Bs[br][bc] =
                *(const float4*)(W + (size_t)(k0 + br) * DD_ + bn0 + bc);
        }
        __syncthreads();

        // ---- FFMA2 inner loop ----
#pragma unroll
        for (int k = 0; k < BK; k++) {
            const float4 a0 = *(const float4*)&As[k][trow * 8];
            const float4 a1 = *(const float4*)&As[k][trow * 8 + 4];
            const ulonglong2 b0 = *(const ulonglong2*)&Bs[k][tcol * 8];      // cols 0..3
            const ulonglong2 b1 = *(const ulonglong2*)&Bs[k][tcol * 8 + 4];  // cols 4..7
            unsigned long long ad[8];
            ad[0] = pack_dup(a0.x); ad[1] = pack_dup(a0.y);
            ad[2] = pack_dup(a0.z); ad[3] = pack_dup(a0.w);
            ad[4] = pack_dup(a1.x); ad[5] = pack_dup(a1.y);
            ad[6] = pack_dup(a1.z); ad[7] = pack_dup(a1.w);
#pragma unroll
            for (int i = 0; i < 8; i++) {
                ffma2(acc[i][0], ad[i], b0.x);
                ffma2(acc[i][1], ad[i], b0.y);
                ffma2(acc[i][2], ad[i], b1.x);
                ffma2(acc[i][3], ad[i], b1.y);
            }
        }
        __syncthreads();
    }

    // ---- epilogue ----
#pragma unroll
    for (int i = 0; i < 8; i++) {
        float2 c0 = unpack2(acc[i][0]);
        float2 c1 = unpack2(acc[i][1]);
        float2 c2 = unpack2(acc[i][2]);
        float2 c3 = unpack2(acc[i][3]);
        float4 r0 = make_float4(c0.x, c0.y, c1.x, c1.y);
        float4 r1 = make_float4(c2.x, c2.y, c3.x, c3.y);
        if (SIG) {
            r0.x = sigmoidf_(r0.x); r0.y = sigmoidf_(r0.y);
            r0.z = sigmoidf_(r0.z); r0.w = sigmoidf_(r0.w);
            r1.x = sigmoidf_(r1.x); r1.y = sigmoidf_(r1.y);
            r1.z = sigmoidf_(r1.z); r1.w = sigmoidf_(r1.w);
        }
        const int m = bm0 + trow * 8 + i;
        float* cp = Cout + (size_t)m * DD_ + bn0 + tcol * 8;
        *(float4*)cp = r0;
        *(float4*)(cp + 4) = r1;
    }
}

// ---------------------------------------------------------------------------
// WKV scan: one thread per (b, d) channel. 8-deep load chunking for MLP.
// Also emits x[:, -1, :] and the new aa/bb/pp carries.
// ---------------------------------------------------------------------------
__global__ void __launch_bounds__(64)
wkv_scan(const float* __restrict__ aa_in, const float* __restrict__ bb_in,
         const float* __restrict__ pp_in, const float* __restrict__ tfv,
         const float* __restrict__ tdv,   const float* __restrict__ x,
         float* __restrict__ outLast, float* __restrict__ outAA,
         float* __restrict__ outBB,  float* __restrict__ outPP)
{
    const int idx = blockIdx.x * blockDim.x + threadIdx.x;  // 0..B*D-1
    const int b = idx / DD_;
    const int d = idx - b * DD_;

    float aa = aa_in[idx], bb = bb_in[idx], pp = pp_in[idx];
    const float tf = tfv[d];
    const float td = tdv[d];

    size_t base = (size_t)b * TT_ * DD_ + d;

    constexpr int CH = 8;
    float kc[CH], vc[CH], rc[CH];

    for (int tb = 0; tb < TT_; tb += CH) {
        // batch-issue 24 independent coalesced loads (MLP)
#pragma unroll
        for (int j = 0; j < CH; j++) {
            size_t o = base + (size_t)j * DD_;
            kc[j] = g_k[o];
            vc[j] = g_v[o];
            rc[j] = g_r[o];
        }
#pragma unroll
        for (int j = 0; j < CH; j++) {
            const float kt = kc[j], vt = vc[j];
            float ww = tf + kt;
            float qq = fmaxf(pp, ww);
            float e1 = __expf(pp - qq);
            float e2 = __expf(ww - qq);
            float wkv = fmaf(e1, aa, e2 * vt) / fmaf(e1, bb, e2);
            g_rwkv[base + (size_t)j * DD_] = rc[j] * wkv;

            float ww2 = pp + td;
            float qq2 = fmaxf(ww2, kt);
            float e1b = __expf(ww2 - qq2);
            float e2b = __expf(kt - qq2);
            aa = fmaf(e1b, aa, e2b * vt);
            bb = fmaf(e1b, bb, e2b);
            pp = qq2;
        }
        base += (size_t)CH * DD_;
    }

    outAA[idx] = aa;
    outBB[idx] = bb;
    outPP[idx] = pp;
    outLast[idx] = x[(size_t)(b * TT_ + TT_ - 1) * DD_ + d];
}

// ---------------------------------------------------------------------------
// Launch: 3 mixed GEMMs -> scan (fused r*wkv + state/lastx emit) -> out GEMM
// Inputs (metadata order): x, last_x, aa, bb, pp, time_mix_k, time_mix_v,
//   time_mix_r, time_first, time_decay, Wk, Wv, Wr, Wo
// Output: [out(M*D)] [lastx(B*D)] [aa] [bb] [pp]
// ---------------------------------------------------------------------------
extern "C" void kernel_launch(void* const* d_in, const int* in_sizes, int n_in,
                              void* d_out, int out_size) {
    const float* x     = (const float*)d_in[0];
    const float* lastx = (const float*)d_in[1];
    const float* aa    = (const float*)d_in[2];
    const float* bb    = (const float*)d_in[3];
    const float* pp    = (const float*)d_in[4];
    const float* tmk   = (const float*)d_in[5];
    const float* tmv   = (const float*)d_in[6];
    const float* tmr   = (const float*)d_in[7];
    const float* tf    = (const float*)d_in[8];
    const float* td    = (const float*)d_in[9];
    const float* Wk    = (const float*)d_in[10];
    const float* Wv    = (const float*)d_in[11];
    const float* Wr    = (const float*)d_in[12];
    const float* Wo    = (const float*)d_in[13];

    float* out = (float*)d_out;

    void *pk, *pv, *pr, *prw, *pdump;
    cudaGetSymbolAddress(&pk, g_k);
    cudaGetSymbolAddress(&pv, g_v);
    cudaGetSymbolAddress(&pr, g_r);
    cudaGetSymbolAddress(&prw, g_rwkv);
    cudaGetSymbolAddress(&pdump, g_dump);

    const int BD = BB_ * DD_;
    float* oLast = out + (size_t)MM_ * DD_;
    float* oAA   = oLast + BD;
    float* oBB   = oAA + BD;
    float* oPP   = oBB + BD;
    if (out_size < MM_ * DD_ + 4 * BD) {   // defensive: only main output present
        oLast = (float*)pdump;
        oAA = oLast + BD; oBB = oAA + BD; oPP = oBB + BD;
        if (out_size < MM_ * DD_ + BD) oLast = (float*)pdump;  // keep in dump
    }

    dim3 ggrid(DD_ / 128, MM_ / 128);   // (8, 128)
    dim3 gblk(256);

    gemm128<true,  false><<<ggrid, gblk>>>(x, lastx, tmk, Wk, (float*)pk);
    gemm128<true,  false><<<ggrid, gblk>>>(x, lastx, tmv, Wv, (float*)pv);
    gemm128<true,  true ><<<ggrid, gblk>>>(x, lastx, tmr, Wr, (float*)pr);

    wkv_scan<<<BD / 64, 64>>>(aa, bb, pp, tf, td, x, oLast, oAA, oBB, oPP);

    gemm128<false, false><<<ggrid, gblk>>>((const float*)prw, nullptr, nullptr,
                                           Wo, out);
}

// round 6
// speedup vs baseline: 2.7857x; 2.7857x over previous
#include <cuda_runtime.h>
#include <cuda_bf16.h>
#include <cstdint>

// Problem constants (fixed by the dataset)
#define BB_  8
#define TT_  2048
#define DD_  1024
#define MM_  (BB_ * TT_)   // 16384

// ---------------------------------------------------------------------------
// Scratch (__device__ globals; no cudaMalloc allowed)
//   packed buffers: fp32 split into bf16 hi/lo packed in a u32 (hi | lo<<16)
// ---------------------------------------------------------------------------
__device__ unsigned g_xk[MM_ * DD_];      // packed mixed xk
__device__ unsigned g_xv[MM_ * DD_];      // packed mixed xv
__device__ unsigned g_xr[MM_ * DD_];      // packed mixed xr
__device__ unsigned g_rw[MM_ * DD_];      // packed r*wkv
__device__ unsigned g_wp[4 * DD_ * DD_];  // packed W^T for Wk,Wv,Wr,Wo
__device__ float    g_k[MM_ * DD_];       // k  (fp32, scan input)
__device__ float    g_v[MM_ * DD_];       // v
__device__ float    g_r[MM_ * DD_];       // sigmoid(r)
__device__ float    g_dump[4 * BB_ * DD_];

// ---------------------------------------------------------------------------
// Helpers
// ---------------------------------------------------------------------------
__device__ __forceinline__ unsigned smem_u32(const void* p) {
    unsigned a;
    asm("{ .reg .u64 t; cvta.to.shared.u64 t, %1; cvt.u32.u64 %0, t; }"
        : "=r"(a) : "l"(p));
    return a;
}
__device__ __forceinline__ unsigned pack_split(float x) {
    __nv_bfloat16 h = __float2bfloat16(x);
    float hf = __bfloat162float(h);
    __nv_bfloat16 l = __float2bfloat16(x - hf);
    return (unsigned)__bfloat16_as_ushort(h) |
           ((unsigned)__bfloat16_as_ushort(l) << 16);
}
__device__ __forceinline__ float sigmoidf_(float x) {
    return 1.0f / (1.0f + __expf(-x));
}
__device__ __forceinline__ void cpasync16(unsigned dst, const void* src) {
    asm volatile("cp.async.cg.shared.global [%0], [%1], 16;"
                 :: "r"(dst), "l"(src));
}
#define CP_COMMIT() asm volatile("cp.async.commit_group;")
#define CP_WAIT(N)  asm volatile("cp.async.wait_group %0;" :: "n"(N))

// mma.sync m16n8k16 row.col bf16 -> f32 (sm_80+, target-portable)
__device__ __forceinline__ void mma16816(float* d, const unsigned* a,
                                         unsigned b0, unsigned b1) {
    asm volatile(
        "mma.sync.aligned.m16n8k16.row.col.f32.bf16.bf16.f32 "
        "{%0,%1,%2,%3}, {%4,%5,%6,%7}, {%8,%9}, {%0,%1,%2,%3};"
        : "+f"(d[0]), "+f"(d[1]), "+f"(d[2]), "+f"(d[3])
        : "r"(a[0]), "r"(a[1]), "r"(a[2]), "r"(a[3]), "r"(b0), "r"(b1));
}

// Load a packed u32 pair (two consecutive k) from a rotated-swizzle tile and
// split into bf16x2 hi / lo fragment registers.
// Tile layout: rows of 32 packed u32 = 128B; 16B chunk c of row r stored at
// chunk ((c + 2r) & 7).  w = even u32 index (k) within the row.
__device__ __forceinline__ void ldpair(unsigned tile, int row, int w,
                                       unsigned& hi, unsigned& lo) {
    unsigned addr = tile + row * 128 + ((((w >> 2) + 2 * row) & 7) << 4)
                    + ((w & 3) << 2);
    unsigned p0, p1;
    asm volatile("ld.shared.v2.u32 {%0,%1}, [%2];"
                 : "=r"(p0), "=r"(p1) : "r"(addr));
    hi = __byte_perm(p0, p1, 0x5410);
    lo = __byte_perm(p0, p1, 0x7632);
}

// ---------------------------------------------------------------------------
// prep_w: Wpack[n*D + k] = pack_split(W[k*D + n])   (4 weight matrices)
// ---------------------------------------------------------------------------
__global__ void prep_w(const float* __restrict__ w0, const float* __restrict__ w1,
                       const float* __restrict__ w2, const float* __restrict__ w3) {
    __shared__ float tile[32][33];
    const float* W = (blockIdx.z == 0) ? w0 : (blockIdx.z == 1) ? w1
                   : (blockIdx.z == 2) ? w2 : w3;
    unsigned* Out = g_wp + (size_t)blockIdx.z * DD_ * DD_;
    int k0 = blockIdx.y * 32, n0 = blockIdx.x * 32;
    tile[threadIdx.y][threadIdx.x] =
        W[(size_t)(k0 + threadIdx.y) * DD_ + n0 + threadIdx.x];
    __syncthreads();
    Out[(size_t)(n0 + threadIdx.y) * DD_ + k0 + threadIdx.x] =
        pack_split(tile[threadIdx.x][threadIdx.y]);
}

// ---------------------------------------------------------------------------
// prep_x: token-shift mixes, packed hi/lo split for the three projections
// ---------------------------------------------------------------------------
__global__ void __launch_bounds__(256)
prep_x(const float* __restrict__ x, const float* __restrict__ lastx,
       const float* __restrict__ tmk, const float* __restrict__ tmv,
       const float* __restrict__ tmr) {
    int idx = blockIdx.x * 256 + threadIdx.x;   // float4 index
    int m = idx >> 8;
    int d = (idx & 255) * 4;
    const float4 xv = *(const float4*)(x + (size_t)m * DD_ + d);
    float4 xp;
    if ((m & (TT_ - 1)) == 0)
        xp = *(const float4*)(lastx + (m >> 11) * DD_ + d);
    else
        xp = *(const float4*)(x + (size_t)(m - 1) * DD_ + d);

    const float4 tk = *(const float4*)(tmk + d);
    const float4 tv = *(const float4*)(tmv + d);
    const float4 tr = *(const float4*)(tmr + d);
    size_t o = (size_t)m * DD_ + d;

    uint4 ok, ov, orr;
    ok.x = pack_split(fmaf(tk.x, xv.x - xp.x, xp.x));
    ok.y = pack_split(fmaf(tk.y, xv.y - xp.y, xp.y));
    ok.z = pack_split(fmaf(tk.z, xv.z - xp.z, xp.z));
    ok.w = pack_split(fmaf(tk.w, xv.w - xp.w, xp.w));
    ov.x = pack_split(fmaf(tv.x, xv.x - xp.x, xp.x));
    ov.y = pack_split(fmaf(tv.y, xv.y - xp.y, xp.y));
    ov.z = pack_split(fmaf(tv.z, xv.z - xp.z, xp.z));
    ov.w = pack_split(fmaf(tv.w, xv.w - xp.w, xp.w));
    orr.x = pack_split(fmaf(tr.x, xv.x - xp.x, xp.x));
    orr.y = pack_split(fmaf(tr.y, xv.y - xp.y, xp.y));
    orr.z = pack_split(fmaf(tr.z, xv.z - xp.z, xp.z));
    orr.w = pack_split(fmaf(tr.w, xv.w - xp.w, xp.w));
    *(uint4*)(g_xk + o) = ok;
    *(uint4*)(g_xv + o) = ov;
    *(uint4*)(g_xr + o) = orr;
}

// ---------------------------------------------------------------------------
// bf16-split GEMM on mma.sync:
//   C[M,1024] = unpack(Ap)[M,1024] * unpack(Bp)[N,1024]^T
//   Ap: [M][K] packed, Bp: [N][K] packed (weights pre-transposed).
//   CTA 128x128, 4 warps (warp tile 64x64), BK=32, 3-stage cp.async pipeline.
//   D = Ah*Bh + Ah*Bl + Al*Bh  (3 mma passes; hi/lo share one LDS.64)
// ---------------------------------------------------------------------------
#define STAGE_BYTES 32768      // A 16KB + B 16KB (packed u32)
#define NSTAGE 3
#define NCHUNK (DD_ / 32)      // 32 BK=32 chunks cover K=1024  (R5 bug: was 16)
#define GEMM_SMEM (NSTAGE * STAGE_BYTES)   // 98304

__device__ __forceinline__ void issue_stage(unsigned stage_base,
                                            const unsigned* __restrict__ Ap,
                                            const unsigned* __restrict__ Bp,
                                            int m0, int n0, int k0u, int tid) {
#pragma unroll
    for (int i = 0; i < 8; i++) {           // A: 128 rows x 8 chunks
        int f = i * 128 + tid;
        int row = f >> 3, c = f & 7;
        unsigned dst = stage_base + row * 128 + (((c + 2 * row) & 7) << 4);
        cpasync16(dst, Ap + (size_t)(m0 + row) * DD_ + k0u + c * 4);
    }
#pragma unroll
    for (int i = 0; i < 8; i++) {           // B
        int f = i * 128 + tid;
        int row = f >> 3, c = f & 7;
        unsigned dst = stage_base + 16384 + row * 128 + (((c + 2 * row) & 7) << 4);
        cpasync16(dst, Bp + (size_t)(n0 + row) * DD_ + k0u + c * 4);
    }
}

template <int SIG>
__global__ void __launch_bounds__(128, 2)
gemm_mma(const unsigned* __restrict__ Ap, const unsigned* __restrict__ Bp,
         float* __restrict__ C) {
    extern __shared__ __align__(128) char smem[];
    const unsigned sb = smem_u32(smem);
    const int tid = threadIdx.x;
    const int lane = tid & 31, warp = tid >> 5;
    const int g = lane >> 2, t = lane & 3;
    const int wm = (warp & 1) * 64;          // warp row offset in CTA tile
    const int wn = (warp >> 1) * 64;         // warp col offset
    const int m0 = blockIdx.y * 128, n0 = blockIdx.x * 128;

    float acc[4][8][4];
#pragma unroll
    for (int i = 0; i < 4; i++)
#pragma unroll
        for (int j = 0; j < 8; j++)
#pragma unroll
            for (int q = 0; q < 4; q++) acc[i][j][q] = 0.0f;

    issue_stage(sb, Ap, Bp, m0, n0, 0, tid);  CP_COMMIT();
    issue_stage(sb + STAGE_BYTES, Ap, Bp, m0, n0, 32, tid);  CP_COMMIT();

    for (int ch = 0; ch < NCHUNK; ch++) {     // 32 BK=32 chunks over K=1024
        CP_WAIT(1);
        __syncthreads();
        if (ch + 2 < NCHUNK)
            issue_stage(sb + ((ch + 2) % NSTAGE) * STAGE_BYTES,
                        Ap, Bp, m0, n0, (ch + 2) * 32, tid);
        CP_COMMIT();

        const unsigned aT = sb + (ch % NSTAGE) * STAGE_BYTES;
        const unsigned bT = aT + 16384;
#pragma unroll
        for (int s = 0; s < 2; s++) {         // two k16 steps per stage
            const int w0 = s * 16 + 2 * t;    // even u32 word index
            unsigned ah[4][4], al[4][4];
#pragma unroll
            for (int i = 0; i < 4; i++) {
                const int r0 = wm + i * 16 + g;
                ldpair(aT, r0,     w0,     ah[i][0], al[i][0]);
                ldpair(aT, r0 + 8, w0,     ah[i][1], al[i][1]);
                ldpair(aT, r0,     w0 + 8, ah[i][2], al[i][2]);
                ldpair(aT, r0 + 8, w0 + 8, ah[i][3], al[i][3]);
            }
#pragma unroll
            for (int j = 0; j < 8; j++) {
                const int rb = wn + j * 8 + g;
                unsigned bh0, bl0, bh1, bl1;
                ldpair(bT, rb, w0,     bh0, bl0);
                ldpair(bT, rb, w0 + 8, bh1, bl1);
#pragma unroll
                for (int i = 0; i < 4; i++) {
                    mma16816(acc[i][j], ah[i], bh0, bh1);
                    mma16816(acc[i][j], ah[i], bl0, bl1);
                    mma16816(acc[i][j], al[i], bh0, bh1);
                }
            }
        }
        __syncthreads();
    }

    // epilogue: accum regs -> C (float2 stores, 32B sectors per thread-quad)
#pragma unroll
    for (int i = 0; i < 4; i++) {
        const int row0 = m0 + wm + i * 16 + g;
#pragma unroll
        for (int j = 0; j < 8; j++) {
            const int col = n0 + wn + j * 8 + 2 * t;
            float2 lo = make_float2(acc[i][j][0], acc[i][j][1]);
            float2 hi = make_float2(acc[i][j][2], acc[i][j][3]);
            if (SIG) {
                lo.x = sigmoidf_(lo.x); lo.y = sigmoidf_(lo.y);
                hi.x = sigmoidf_(hi.x); hi.y = sigmoidf_(hi.y);
            }
            *(float2*)(C + (size_t)row0 * DD_ + col) = lo;
            *(float2*)(C + (size_t)(row0 + 8) * DD_ + col) = hi;
        }
    }
}

// ---------------------------------------------------------------------------
// WKV scan: one thread per (b,d) channel, software-pipelined 8-deep chunks.
// Emits packed r*wkv for the out-GEMM plus states and x[:, -1, :].
// ---------------------------------------------------------------------------
struct ScanState { float aa, bb, pp, tf, td; };

__device__ __forceinline__ void scan_steps(ScanState& s, const float* kc,
                                           const float* vc, const float* rc,
                                           unsigned* rw, size_t base) {
#pragma unroll
    for (int j = 0; j < 8; j++) {
        const float kt = kc[j], vt = vc[j];
        float ww = s.tf + kt;
        float qq = fmaxf(s.pp, ww);
        float e1 = __expf(s.pp - qq);
        float e2 = __expf(ww - qq);
        float wkv = fmaf(e1, s.aa, e2 * vt) / fmaf(e1, s.bb, e2);
        rw[base + (size_t)j * DD_] = pack_split(rc[j] * wkv);

        float ww2 = s.pp + s.td;
        float qq2 = fmaxf(ww2, kt);
        float e1b = __expf(ww2 - qq2);
        float e2b = __expf(kt - qq2);
        s.aa = fmaf(e1b, s.aa, e2b * vt);
        s.bb = fmaf(e1b, s.bb, e2b);
        s.pp = qq2;
    }
}

__global__ void __launch_bounds__(64)
wkv_scan(const float* __restrict__ aa_in, const float* __restrict__ bb_in,
         const float* __restrict__ pp_in, const float* __restrict__ tfv,
         const float* __restrict__ tdv,   const float* __restrict__ x,
         float* __restrict__ outLast, float* __restrict__ outAA,
         float* __restrict__ outBB,  float* __restrict__ outPP) {
    const int idx = blockIdx.x * 64 + threadIdx.x;  // 0..B*D-1
    const int b = idx / DD_;
    const int d = idx - b * DD_;

    ScanState s;
    s.aa = aa_in[idx]; s.bb = bb_in[idx]; s.pp = pp_in[idx];
    s.tf = tfv[d];     s.td = tdv[d];

    const size_t base0 = (size_t)b * TT_ * DD_ + d;
    float ka[8], va[8], ra[8], kb[8], vb[8], rb[8];

#pragma unroll
    for (int j = 0; j < 8; j++) {
        size_t o = base0 + (size_t)j * DD_;
        ka[j] = g_k[o]; va[j] = g_v[o]; ra[j] = g_r[o];
    }

    for (int tb = 0; tb < TT_; tb += 16) {
        size_t baseA = base0 + (size_t)tb * DD_;
        size_t baseB = baseA + (size_t)8 * DD_;
#pragma unroll
        for (int j = 0; j < 8; j++) {        // prefetch next chunk
            size_t o = baseB + (size_t)j * DD_;
            kb[j] = g_k[o]; vb[j] = g_v[o]; rb[j] = g_r[o];
        }
        scan_steps(s, ka, va, ra, g_rw, baseA);
        if (tb + 16 < TT_) {
            size_t baseC = baseA + (size_t)16 * DD_;
#pragma unroll
            for (int j = 0; j < 8; j++) {
                size_t o = baseC + (size_t)j * DD_;
                ka[j] = g_k[o]; va[j] = g_v[o]; ra[j] = g_r[o];
            }
        }
        scan_steps(s, kb, vb, rb, g_rw, baseB);
    }

    outAA[idx] = s.aa;
    outBB[idx] = s.bb;
    outPP[idx] = s.pp;
    outLast[idx] = x[(size_t)(b * TT_ + TT_ - 1) * DD_ + d];
}

// ---------------------------------------------------------------------------
// Launch: prep_w + prep_x -> 3 mma GEMMs -> scan -> out mma GEMM
// Inputs (metadata order): x, last_x, aa, bb, pp, time_mix_k, time_mix_v,
//   time_mix_r, time_first, time_decay, Wk, Wv, Wr, Wo
// Output: [out(M*D)] [lastx(B*D)] [aa] [bb] [pp]
// ---------------------------------------------------------------------------
extern "C" void kernel_launch(void* const* d_in, const int* in_sizes, int n_in,
                              void* d_out, int out_size) {
    const float* x     = (const float*)d_in[0];
    const float* lastx = (const float*)d_in[1];
    const float* aa    = (const float*)d_in[2];
    const float* bb    = (const float*)d_in[3];
    const float* pp    = (const float*)d_in[4];
    const float* tmk   = (const float*)d_in[5];
    const float* tmv   = (const float*)d_in[6];
    const float* tmr   = (const float*)d_in[7];
    const float* tf    = (const float*)d_in[8];
    const float* td    = (const float*)d_in[9];
    const float* Wk    = (const float*)d_in[10];
    const float* Wv    = (const float*)d_in[11];
    const float* Wr    = (const float*)d_in[12];
    const float* Wo    = (const float*)d_in[13];

    float* out = (float*)d_out;

    void *pxk, *pxv, *pxr, *prw, *pwp, *pk, *pv, *pr, *pdump;
    cudaGetSymbolAddress(&pxk, g_xk);
    cudaGetSymbolAddress(&pxv, g_xv);
    cudaGetSymbolAddress(&pxr, g_xr);
    cudaGetSymbolAddress(&prw, g_rw);
    cudaGetSymbolAddress(&pwp, g_wp);
    cudaGetSymbolAddress(&pk, g_k);
    cudaGetSymbolAddress(&pv, g_v);
    cudaGetSymbolAddress(&pr, g_r);
    cudaGetSymbolAddress(&pdump, g_dump);

    cudaFuncSetAttribute(gemm_mma<0>, cudaFuncAttributeMaxDynamicSharedMemorySize,
                         GEMM_SMEM);
    cudaFuncSetAttribute(gemm_mma<1>, cudaFuncAttributeMaxDynamicSharedMemorySize,
                         GEMM_SMEM);

    const int BD = BB_ * DD_;
    float* oLast = out + (size_t)MM_ * DD_;
    float* oAA   = oLast + BD;
    float* oBB   = oAA + BD;
    float* oPP   = oBB + BD;
    if (out_size < MM_ * DD_ + 4 * BD) {
        oLast = (float*)pdump;
        oAA = oLast + BD; oBB = oAA + BD; oPP = oBB + BD;
    }

    const unsigned* wp = (const unsigned*)pwp;

    prep_w<<<dim3(32, 32, 4), dim3(32, 32)>>>(Wk, Wv, Wr, Wo);
    prep_x<<<MM_ * DD_ / 4 / 256, 256>>>(x, lastx, tmk, tmv, tmr);

    dim3 ggrid(DD_ / 128, MM_ / 128);   // (8, 128)
    gemm_mma<0><<<ggrid, 128, GEMM_SMEM>>>((const unsigned*)pxk,
                                           wp + 0 * (size_t)DD_ * DD_, (float*)pk);
    gemm_mma<0><<<ggrid, 128, GEMM_SMEM>>>((const unsigned*)pxv,
                                           wp + 1 * (size_t)DD_ * DD_, (float*)pv);
    gemm_mma<1><<<ggrid, 128, GEMM_SMEM>>>((const unsigned*)pxr,
                                           wp + 2 * (size_t)DD_ * DD_, (float*)pr);

    wkv_scan<<<BD / 64, 64>>>(aa, bb, pp, tf, td, x, oLast, oAA, oBB, oPP);

    gemm_mma<0><<<ggrid, 128, GEMM_SMEM>>>((const unsigned*)prw,
                                           wp + 3 * (size_t)DD_ * DD_, out);
}

// round 9
// speedup vs baseline: 3.6588x; 1.3134x over previous
#include <cuda_runtime.h>
#include <cuda_fp16.h>
#include <cstdint>

// Problem constants (fixed by the dataset)
#define BB_   8
#define TT_   2048
#define DD_   1024
#define MM_   (BB_ * TT_)    // 16384
#define BD_   (BB_ * DD_)    // 8192
#define NSEG  8
#define SEGLEN (TT_ / NSEG)  // 256

// ---------------------------------------------------------------------------
// Scratch (__device__ globals; no cudaMalloc allowed)
//   g_x* / g_rw: fp32 split into fp16 hi/lo packed in u32 (hi | lo<<16),
//                stored with k-interleaved order within 16-groups.
//   g_wp: plain fp16 W^T, same k-interleaving.
// ---------------------------------------------------------------------------
__device__ unsigned g_xk[MM_ * DD_];
__device__ unsigned g_xv[MM_ * DD_];
__device__ unsigned g_xr[MM_ * DD_];
__device__ unsigned g_rw[MM_ * DD_];
__device__ __half   g_wp[4 * DD_ * DD_];
__device__ float    g_k[MM_ * DD_];
__device__ float    g_v[MM_ * DD_];
__device__ float    g_r[MM_ * DD_];
// parallel-scan workspace
__device__ float g_sa[NSEG][BD_], g_sb[NSEG][BD_], g_sp[NSEG][BD_];
__device__ float g_ia[NSEG][BD_], g_ib[NSEG][BD_], g_ip[NSEG][BD_];
__device__ float g_dump[4 * BD_];

// ---------------------------------------------------------------------------
// Helpers
// ---------------------------------------------------------------------------
// k-interleave within a 16-group: position order [0,1,8,9, 2,3,10,11, ...]
// pos16(k) = destination slot of source k (k in 0..15)
__device__ __forceinline__ int pos16(int k) {
    return ((k & 6) << 1) | (k & 1) | (((k >> 3) & 1) << 1);
}
__device__ __forceinline__ unsigned smem_u32(const void* p) {
    unsigned a;
    asm("{ .reg .u64 t; cvta.to.shared.u64 t, %1; cvt.u32.u64 %0, t; }"
        : "=r"(a) : "l"(p));
    return a;
}
__device__ __forceinline__ unsigned pack_split16(float x) {
    __half h = __float2half_rn(x);
    float hf = __half2float(h);
    __half l = __float2half_rn(x - hf);
    return (unsigned)__half_as_ushort(h) | ((unsigned)__half_as_ushort(l) << 16);
}
__device__ __forceinline__ float sigmoidf_(float x) {
    return 1.0f / (1.0f + __expf(-x));
}
__device__ __forceinline__ void cpasync16(unsigned dst, const void* src) {
    asm volatile("cp.async.cg.shared.global [%0], [%1], 16;"
                 :: "r"(dst), "l"(src));
}
#define CP_COMMIT() asm volatile("cp.async.commit_group;")
#define CP_WAIT(N)  asm volatile("cp.async.wait_group %0;" :: "n"(N))

__device__ __forceinline__ uint4 lds128(unsigned a) {
    uint4 q;
    asm volatile("ld.shared.v4.u32 {%0,%1,%2,%3}, [%4];"
                 : "=r"(q.x), "=r"(q.y), "=r"(q.z), "=r"(q.w) : "r"(a));
    return q;
}
__device__ __forceinline__ uint2 lds64(unsigned a) {
    uint2 q;
    asm volatile("ld.shared.v2.u32 {%0,%1}, [%2];"
                 : "=r"(q.x), "=r"(q.y) : "r"(a));
    return q;
}

// mma.sync m16n8k16 row.col fp16 -> f32 (sm_80+, target-portable)
__device__ __forceinline__ void mma16816h(float* d, const unsigned* a,
                                          unsigned b0, unsigned b1) {
    asm volatile(
        "mma.sync.aligned.m16n8k16.row.col.f32.f16.f16.f32 "
        "{%0,%1,%2,%3}, {%4,%5,%6,%7}, {%8,%9}, {%0,%1,%2,%3};"
        : "+f"(d[0]), "+f"(d[1]), "+f"(d[2]), "+f"(d[3])
        : "r"(a[0]), "r"(a[1]), "r"(a[2]), "r"(a[3]), "r"(b0), "r"(b1));
}

// ---------------------------------------------------------------------------
// prep_w: Wp[n*D + ilv(k)] = fp16(W[k*D + n])  (4 matrices, k-interleaved)
// ---------------------------------------------------------------------------
__global__ void prep_w(const float* __restrict__ w0, const float* __restrict__ w1,
                       const float* __restrict__ w2, const float* __restrict__ w3) {
    __shared__ float tile[32][33];
    const float* W = (blockIdx.z == 0) ? w0 : (blockIdx.z == 1) ? w1
                   : (blockIdx.z == 2) ? w2 : w3;
    __half* Out = g_wp + (size_t)blockIdx.z * DD_ * DD_;
    int k0 = blockIdx.y * 32, n0 = blockIdx.x * 32;
    tile[threadIdx.y][threadIdx.x] =
        W[(size_t)(k0 + threadIdx.y) * DD_ + n0 + threadIdx.x];
    __syncthreads();
    int kk = threadIdx.x;                       // local k 0..31
    int dstk = k0 + (kk & 16) + pos16(kk & 15);
    Out[(size_t)(n0 + threadIdx.y) * DD_ + dstk] =
        __float2half_rn(tile[threadIdx.x][threadIdx.y]);
}

// ---------------------------------------------------------------------------
// prep_x: token-shift mixes, fp16 hi/lo packed, k-interleaved positions
// ---------------------------------------------------------------------------
__global__ void __launch_bounds__(256)
prep_x(const float* __restrict__ x, const float* __restrict__ lastx,
       const float* __restrict__ tmk, const float* __restrict__ tmv,
       const float* __restrict__ tmr) {
    int idx = blockIdx.x * 256 + threadIdx.x;   // float4 index
    int m = idx >> 8;
    int d = (idx & 255) * 4;                    // d multiple of 4
    const float4 xv = *(const float4*)(x + (size_t)m * DD_ + d);
    float4 xp;
    if ((m & (TT_ - 1)) == 0)
        xp = *(const float4*)(lastx + (m >> 11) * DD_ + d);
    else
        xp = *(const float4*)(x + (size_t)(m - 1) * DD_ + d);

    const float4 tk = *(const float4*)(tmk + d);
    const float4 tv = *(const float4*)(tmv + d);
    const float4 tr = *(const float4*)(tmr + d);

    float xd[4] = {xv.x - xp.x, xv.y - xp.y, xv.z - xp.z, xv.w - xp.w};
    float xb[4] = {xp.x, xp.y, xp.z, xp.w};
    float fk[4] = {tk.x, tk.y, tk.z, tk.w};
    float fv[4] = {tv.x, tv.y, tv.z, tv.w};
    float fr[4] = {tr.x, tr.y, tr.z, tr.w};

    size_t gbase = (size_t)m * DD_ + (d & ~15);
#pragma unroll
    for (int e = 0; e < 4; e++) {
        int p = pos16((d & 15) + e);
        g_xk[gbase + p] = pack_split16(fmaf(fk[e], xd[e], xb[e]));
        g_xv[gbase + p] = pack_split16(fmaf(fv[e], xd[e], xb[e]));
        g_xr[gbase + p] = pack_split16(fmaf(fr[e], xd[e], xb[e]));
    }
}

// ---------------------------------------------------------------------------
// fp16 split-2 GEMM on mma.sync:
//   C[M,1024] = (Ahi+Alo)[M,1024] * Bfp16[N,1024]^T
//   A: packed u32 (hi|lo), B: plain fp16 (weights, pre-transposed).
//   CTA 128x128, 4 warps (64x64 warp tile), BK=32, 3-stage cp.async.
//   Smem: A rows 128B, chunk swizzle c^=((row&1)<<2); B rows 64B, c'=(c+row)&3.
// ---------------------------------------------------------------------------
#define A_STAGE 16384
#define B_STAGE 8192
#define STAGE_BYTES (A_STAGE + B_STAGE)     // 24576
#define NSTAGE 3
#define NCHUNK (DD_ / 32)                   // 32
#define GEMM_SMEM (NSTAGE * STAGE_BYTES)    // 73728

__device__ __forceinline__ void issue_stage(unsigned stage_base,
                                            const unsigned* __restrict__ Ap,
                                            const __half* __restrict__ Bp,
                                            int m0, int n0, int k0u, int tid) {
#pragma unroll
    for (int i = 0; i < 8; i++) {            // A: 128 rows x 8 chunks(16B)
        int f = i * 128 + tid;
        int row = f >> 3, c = f & 7;
        unsigned dst = stage_base + row * 128 + ((c ^ ((row & 1) << 2)) << 4);
        cpasync16(dst, Ap + (size_t)(m0 + row) * DD_ + k0u + c * 4);
    }
#pragma unroll
    for (int i = 0; i < 4; i++) {            // B: 128 rows x 4 chunks(16B)
        int f = i * 128 + tid;
        int row = f >> 2, c = f & 3;
        unsigned dst = stage_base + A_STAGE + row * 64 + (((c + row) & 3) << 4);
        cpasync16(dst, Bp + (size_t)(n0 + row) * DD_ + k0u + c * 8);
    }
}

template <int SIG>
__global__ void __launch_bounds__(128, 2)
gemm_mma(const unsigned* __restrict__ Ap, const __half* __restrict__ Bp,
         float* __restrict__ C) {
    extern __shared__ __align__(128) char smem[];
    const unsigned sb = smem_u32(smem);
    const int tid = threadIdx.x;
    const int lane = tid & 31, warp = tid >> 5;
    const int g = lane >> 2, t = lane & 3;
    const int wm = (warp & 1) * 64;
    const int wn = (warp >> 1) * 64;
    const int m0 = blockIdx.y * 128, n0 = blockIdx.x * 128;
    const unsigned axor = (g & 1) << 2;      // A chunk swizzle (row parity = g&1)

    float acc[4][8][4];
#pragma unroll
    for (int i = 0; i < 4; i++)
#pragma unroll
        for (int j = 0; j < 8; j++)
#pragma unroll
            for (int q = 0; q < 4; q++) acc[i][j][q] = 0.0f;

    issue_stage(sb, Ap, Bp, m0, n0, 0, tid);  CP_COMMIT();
    issue_stage(sb + STAGE_BYTES, Ap, Bp, m0, n0, 32, tid);  CP_COMMIT();

    for (int ch = 0; ch < NCHUNK; ch++) {
        CP_WAIT(1);
        __syncthreads();
        if (ch + 2 < NCHUNK)
            issue_stage(sb + ((ch + 2) % NSTAGE) * STAGE_BYTES,
                        Ap, Bp, m0, n0, (ch + 2) * 32, tid);
        CP_COMMIT();

        const unsigned aT = sb + (ch % NSTAGE) * STAGE_BYTES;
        const unsigned bT = aT + A_STAGE;
#pragma unroll
        for (int s = 0; s < 2; s++) {         // two k16 steps per BK=32 stage
            const unsigned cA = (unsigned)(4 * s + t) ^ axor;   // A chunk
            const unsigned cBs = ((unsigned)(2 * s + (t >> 1) + g) & 3);
            const unsigned bOff = (cBs << 4) + ((t & 1) << 3);

            unsigned ah[4][4], al[4][4];
#pragma unroll
            for (int i = 0; i < 4; i++) {
                const int r0 = wm + i * 16 + g;
                uint4 q0 = lds128(aT + r0 * 128 + (cA << 4));
                uint4 q1 = lds128(aT + (r0 + 8) * 128 + (cA << 4));
                ah[i][0] = __byte_perm(q0.x, q0.y, 0x5410);
                al[i][0] = __byte_perm(q0.x, q0.y, 0x7632);
                ah[i][2] = __byte_perm(q0.z, q0.w, 0x5410);
                al[i][2] = __byte_perm(q0.z, q0.w, 0x7632);
                ah[i][1] = __byte_perm(q1.x, q1.y, 0x5410);
                al[i][1] = __byte_perm(q1.x, q1.y, 0x7632);
                ah[i][3] = __byte_perm(q1.z, q1.w, 0x5410);
                al[i][3] = __byte_perm(q1.z, q1.w, 0x7632);
            }
#pragma unroll
            for (int j = 0; j < 8; j++) {
                const int rb = wn + j * 8 + g;
                uint2 qb = lds64(bT + rb * 64 + bOff);
#pragma unroll
                for (int i = 0; i < 4; i++) {
                    mma16816h(acc[i][j], ah[i], qb.x, qb.y);
                    mma16816h(acc[i][j], al[i], qb.x, qb.y);
                }
            }
        }
        __syncthreads();
    }

    // epilogue (same accum layout as R6)
#pragma unroll
    for (int i = 0; i < 4; i++) {
        const int row0 = m0 + wm + i * 16 + g;
#pragma unroll
        for (int j = 0; j < 8; j++) {
            const int col = n0 + wn + j * 8 + 2 * t;
            float2 lo = make_float2(acc[i][j][0], acc[i][j][1]);
            float2 hi = make_float2(acc[i][j][2], acc[i][j][3]);
            if (SIG) {
                lo.x = sigmoidf_(lo.x); lo.y = sigmoidf_(lo.y);
                hi.x = sigmoidf_(hi.x); hi.y = sigmoidf_(hi.y);
            }
            *(float2*)(C + (size_t)row0 * DD_ + col) = lo;
            *(float2*)(C + (size_t)(row0 + 8) * DD_ + col) = hi;
        }
    }
}

// ---------------------------------------------------------------------------
// Parallel WKV scan: 8 segments of 256 steps.
//   phase1: per-(channel,segment) summary with zero init (state-only)
//   combine: sequential composition over 8 segments (log-stabilized affine)
//   phase2: re-scan each segment from composed init, emit packed r*wkv
// ---------------------------------------------------------------------------
__global__ void __launch_bounds__(128)
wkv_phase1(const float* __restrict__ tdv) {
    const int idx = blockIdx.x * 128 + threadIdx.x;  // 0..NSEG*BD_-1
    const int c = idx & (BD_ - 1);
    const int seg = idx >> 13;
    const int b = c >> 10;
    const int d = c & (DD_ - 1);
    const float td = tdv[d];

    float aa = 0.f, bb = 0.f, pp = -1e30f;
    size_t base = ((size_t)b * TT_ + seg * SEGLEN) * DD_ + d;
    float kc[8], vc[8];
    for (int tb = 0; tb < SEGLEN; tb += 8) {
#pragma unroll
        for (int j = 0; j < 8; j++) {
            kc[j] = g_k[base + (size_t)j * DD_];
            vc[j] = g_v[base + (size_t)j * DD_];
        }
#pragma unroll
        for (int j = 0; j < 8; j++) {
            const float kt = kc[j], vt = vc[j];
            float ww2 = pp + td;
            float qq2 = fmaxf(ww2, kt);
            float e1b = __expf(ww2 - qq2);
            float e2b = __expf(kt - qq2);
            aa = fmaf(e1b, aa, e2b * vt);
            bb = fmaf(e1b, bb, e2b);
            pp = qq2;
        }
        base += (size_t)8 * DD_;
    }
    g_sa[seg][c] = aa; g_sb[seg][c] = bb; g_sp[seg][c] = pp;
}

__global__ void __launch_bounds__(128)
wkv_combine(const float* __restrict__ aa_in, const float* __restrict__ bb_in,
            const float* __restrict__ pp_in, const float* __restrict__ tdv,
            const float* __restrict__ x,
            float* __restrict__ outLast, float* __restrict__ outAA,
            float* __restrict__ outBB,  float* __restrict__ outPP) {
    const int c = blockIdx.x * 128 + threadIdx.x;    // 0..BD_-1
    const int b = c >> 10;
    const int d = c & (DD_ - 1);
    const float decay = (float)SEGLEN * tdv[d];

    float a = aa_in[c], bq = bb_in[c], p = pp_in[c];
#pragma unroll
    for (int s = 0; s < NSEG; s++) {
        g_ia[s][c] = a; g_ib[s][c] = bq; g_ip[s][c] = p;
        float pd = p + decay;
        float sp = g_sp[s][c];
        float pn = fmaxf(pd, sp);
        float e1 = __expf(pd - pn);
        float e2 = __expf(sp - pn);
        a  = fmaf(e1, a,  e2 * g_sa[s][c]);
        bq = fmaf(e1, bq, e2 * g_sb[s][c]);
        p = pn;
    }
    outAA[c] = a; outBB[c] = bq; outPP[c] = p;
    outLast[c] = x[((size_t)b * TT_ + TT_ - 1) * DD_ + d];
}

__global__ void __launch_bounds__(128)
wkv_phase2(const float* __restrict__ tfv, const float* __restrict__ tdv) {
    const int idx = blockIdx.x * 128 + threadIdx.x;
    const int c = idx & (BD_ - 1);
    const int seg = idx >> 13;
    const int b = c >> 10;
    const int d = c & (DD_ - 1);
    const float tf = tfv[d], td = tdv[d];

    float aa = g_ia[seg][c], bb = g_ib[seg][c], pp = g_ip[seg][c];
    size_t base = ((size_t)b * TT_ + seg * SEGLEN) * DD_ + d;
    const int dI = (d & ~15) | pos16(d & 15);
    size_t rwb = ((size_t)b * TT_ + seg * SEGLEN) * DD_ + dI;

    float kc[8], vc[8], rc[8];
    for (int tb = 0; tb < SEGLEN; tb += 8) {
#pragma unroll
        for (int j = 0; j < 8; j++) {
            kc[j] = g_k[base + (size_t)j * DD_];
            vc[j] = g_v[base + (size_t)j * DD_];
            rc[j] = g_r[base + (size_t)j * DD_];
        }
#pragma unroll
        for (int j = 0; j < 8; j++) {
            const float kt = kc[j], vt = vc[j];
            float ww = tf + kt;
            float qq = fmaxf(pp, ww);
            float e1 = __expf(pp - qq);
            float e2 = __expf(ww - qq);
            float wkv = fmaf(e1, aa, e2 * vt) / fmaf(e1, bb, e2);
            g_rw[rwb + (size_t)j * DD_] = pack_split16(rc[j] * wkv);

            float ww2 = pp + td;
            float qq2 = fmaxf(ww2, kt);
            float e1b = __expf(ww2 - qq2);
            float e2b = __expf(kt - qq2);
            aa = fmaf(e1b, aa, e2b * vt);
            bb = fmaf(e1b, bb, e2b);
            pp = qq2;
        }
        base += (size_t)8 * DD_;
        rwb  += (size_t)8 * DD_;
    }
}

// ---------------------------------------------------------------------------
// Launch. Inputs (metadata order): x, last_x, aa, bb, pp, time_mix_k,
//   time_mix_v, time_mix_r, time_first, time_decay, Wk, Wv, Wr, Wo
// Output: [out(M*D)] [lastx(B*D)] [aa] [bb] [pp]
// ---------------------------------------------------------------------------
extern "C" void kernel_launch(void* const* d_in, const int* in_sizes, int n_in,
                              void* d_out, int out_size) {
    const float* x     = (const float*)d_in[0];
    const float* lastx = (const float*)d_in[1];
    const float* aa    = (const float*)d_in[2];
    const float* bb    = (const float*)d_in[3];
    const float* pp    = (const float*)d_in[4];
    const float* tmk   = (const float*)d_in[5];
    const float* tmv   = (const float*)d_in[6];
    const float* tmr   = (const float*)d_in[7];
    const float* tf    = (const float*)d_in[8];
    const float* td    = (const float*)d_in[9];
    const float* Wk    = (const float*)d_in[10];
    const float* Wv    = (const float*)d_in[11];
    const float* Wr    = (const float*)d_in[12];
    const float* Wo    = (const float*)d_in[13];

    float* out = (float*)d_out;

    void *pxk, *pxv, *pxr, *prw, *pwp, *pk, *pv, *pr, *pdump;
    cudaGetSymbolAddress(&pxk, g_xk);
    cudaGetSymbolAddress(&pxv, g_xv);
    cudaGetSymbolAddress(&pxr, g_xr);
    cudaGetSymbolAddress(&prw, g_rw);
    cudaGetSymbolAddress(&pwp, g_wp);
    cudaGetSymbolAddress(&pk, g_k);
    cudaGetSymbolAddress(&pv, g_v);
    cudaGetSymbolAddress(&pr, g_r);
    cudaGetSymbolAddress(&pdump, g_dump);

    cudaFuncSetAttribute(gemm_mma<0>, cudaFuncAttributeMaxDynamicSharedMemorySize,
                         GEMM_SMEM);
    cudaFuncSetAttribute(gemm_mma<1>, cudaFuncAttributeMaxDynamicSharedMemorySize,
                         GEMM_SMEM);

    float* oLast = out + (size_t)MM_ * DD_;
    float* oAA   = oLast + BD_;
    float* oBB   = oAA + BD_;
    float* oPP   = oBB + BD_;
    if (out_size < MM_ * DD_ + 4 * BD_) {
        oLast = (float*)pdump;
        oAA = oLast + BD_; oBB = oAA + BD_; oPP = oBB + BD_;
    }

    const __half* wp = (const __half*)pwp;

    prep_w<<<dim3(32, 32, 4), dim3(32, 32)>>>(Wk, Wv, Wr, Wo);
    prep_x<<<MM_ * DD_ / 4 / 256, 256>>>(x, lastx, tmk, tmv, tmr);

    dim3 ggrid(DD_ / 128, MM_ / 128);   // (8, 128)
    gemm_mma<0><<<ggrid, 128, GEMM_SMEM>>>((const unsigned*)pxk,
                                           wp + 0 * (size_t)DD_ * DD_, (float*)pk);
    gemm_mma<0><<<ggrid, 128, GEMM_SMEM>>>((const unsigned*)pxv,
                                           wp + 1 * (size_t)DD_ * DD_, (float*)pv);
    gemm_mma<1><<<ggrid, 128, GEMM_SMEM>>>((const unsigned*)pxr,
                                           wp + 2 * (size_t)DD_ * DD_, (float*)pr);

    wkv_phase1<<<NSEG * BD_ / 128, 128>>>(td);
    wkv_combine<<<BD_ / 128, 128>>>(aa, bb, pp, td, x, oLast, oAA, oBB, oPP);
    wkv_phase2<<<NSEG * BD_ / 128, 128>>>(tf, td);

    gemm_mma<0><<<ggrid, 128, GEMM_SMEM>>>((const unsigned*)prw,
                                           wp + 3 * (size_t)DD_ * DD_, out);
}

// round 11
// speedup vs baseline: 3.7890x; 1.0356x over previous
#include <cuda_runtime.h>
#include <cuda_fp16.h>
#include <cstdint>

// Problem constants (fixed by the dataset)
#define BB_   8
#define TT_   2048
#define DD_   1024
#define MM_   (BB_ * TT_)    // 16384
#define BD_   (BB_ * DD_)    // 8192
#define NSEG  8
#define SEGLEN (TT_ / NSEG)  // 256

// ---------------------------------------------------------------------------
// Scratch (__device__ globals; no cudaMalloc allowed)
// ---------------------------------------------------------------------------
__device__ unsigned g_xk[MM_ * DD_];
__device__ unsigned g_xv[MM_ * DD_];
__device__ unsigned g_xr[MM_ * DD_];
__device__ unsigned g_rw[MM_ * DD_];
__device__ __half   g_wp[4 * DD_ * DD_];
__device__ float    g_k[MM_ * DD_];
__device__ float    g_v[MM_ * DD_];
__device__ float    g_r[MM_ * DD_];
// parallel-scan workspace
__device__ float g_sa[NSEG][BD_], g_sb[NSEG][BD_], g_sp[NSEG][BD_];
__device__ float g_ia[NSEG][BD_], g_ib[NSEG][BD_], g_ip[NSEG][BD_];
__device__ float g_dump[4 * BD_];

// ---------------------------------------------------------------------------
// Helpers
// ---------------------------------------------------------------------------
// k-interleave within a 16-group: [k,k+1,k+8,k+9] quads contiguous
__device__ __forceinline__ int pos16(int k) {
    return ((k & 6) << 1) | (k & 1) | (((k >> 3) & 1) << 1);
}
__device__ __forceinline__ unsigned smem_u32(const void* p) {
    unsigned a;
    asm("{ .reg .u64 t; cvta.to.shared.u64 t, %1; cvt.u32.u64 %0, t; }"
        : "=r"(a) : "l"(p));
    return a;
}
__device__ __forceinline__ unsigned pack_split16(float x) {
    __half h = __float2half_rn(x);
    float hf = __half2float(h);
    __half l = __float2half_rn(x - hf);
    return (unsigned)__half_as_ushort(h) | ((unsigned)__half_as_ushort(l) << 16);
}
__device__ __forceinline__ float sigmoidf_(float x) {
    return 1.0f / (1.0f + __expf(-x));
}
__device__ __forceinline__ void cpasync16(unsigned dst, const void* src) {
    asm volatile("cp.async.cg.shared.global [%0], [%1], 16;"
                 :: "r"(dst), "l"(src));
}
#define CP_COMMIT() asm volatile("cp.async.commit_group;")
#define CP_WAIT(N)  asm volatile("cp.async.wait_group %0;" :: "n"(N))

__device__ __forceinline__ uint4 lds128(unsigned a) {
    uint4 q;
    asm volatile("ld.shared.v4.u32 {%0,%1,%2,%3}, [%4];"
                 : "=r"(q.x), "=r"(q.y), "=r"(q.z), "=r"(q.w) : "r"(a));
    return q;
}
__device__ __forceinline__ uint2 lds64(unsigned a) {
    uint2 q;
    asm volatile("ld.shared.v2.u32 {%0,%1}, [%2];"
                 : "=r"(q.x), "=r"(q.y) : "r"(a));
    return q;
}

// mma.sync m16n8k16 row.col fp16 -> f32
__device__ __forceinline__ void mma16816h(float* d, const unsigned* a,
                                          unsigned b0, unsigned b1) {
    asm volatile(
        "mma.sync.aligned.m16n8k16.row.col.f32.f16.f16.f32 "
        "{%0,%1,%2,%3}, {%4,%5,%6,%7}, {%8,%9}, {%0,%1,%2,%3};"
        : "+f"(d[0]), "+f"(d[1]), "+f"(d[2]), "+f"(d[3])
        : "r"(a[0]), "r"(a[1]), "r"(a[2]), "r"(a[3]), "r"(b0), "r"(b1));
}

// ---------------------------------------------------------------------------
// prep_w: Wp[n*D + ilv(k)] = fp16(W[k*D + n])  (4 matrices, k-interleaved)
// ---------------------------------------------------------------------------
__global__ void prep_w(const float* __restrict__ w0, const float* __restrict__ w1,
                       const float* __restrict__ w2, const float* __restrict__ w3) {
    __shared__ float tile[32][33];
    const float* W = (blockIdx.z == 0) ? w0 : (blockIdx.z == 1) ? w1
                   : (blockIdx.z == 2) ? w2 : w3;
    __half* Out = g_wp + (size_t)blockIdx.z * DD_ * DD_;
    int k0 = blockIdx.y * 32, n0 = blockIdx.x * 32;
    tile[threadIdx.y][threadIdx.x] =
        W[(size_t)(k0 + threadIdx.y) * DD_ + n0 + threadIdx.x];
    __syncthreads();
    int kk = threadIdx.x;
    int dstk = k0 + (kk & 16) + pos16(kk & 15);
    Out[(size_t)(n0 + threadIdx.y) * DD_ + dstk] =
        __float2half_rn(tile[threadIdx.x][threadIdx.y]);
}

// ---------------------------------------------------------------------------
// prep_x: token-shift mixes, fp16 hi/lo packed, k-interleaved positions
// ---------------------------------------------------------------------------
__global__ void __launch_bounds__(256)
prep_x(const float* __restrict__ x, const float* __restrict__ lastx,
       const float* __restrict__ tmk, const float* __restrict__ tmv,
       const float* __restrict__ tmr) {
    int idx = blockIdx.x * 256 + threadIdx.x;   // float4 index
    int m = idx >> 8;
    int d = (idx & 255) * 4;
    const float4 xv = *(const float4*)(x + (size_t)m * DD_ + d);
    float4 xp;
    if ((m & (TT_ - 1)) == 0)
        xp = *(const float4*)(lastx + (m >> 11) * DD_ + d);
    else
        xp = *(const float4*)(x + (size_t)(m - 1) * DD_ + d);

    const float4 tk = *(const float4*)(tmk + d);
    const float4 tv = *(const float4*)(tmv + d);
    const float4 tr = *(const float4*)(tmr + d);

    float xd[4] = {xv.x - xp.x, xv.y - xp.y, xv.z - xp.z, xv.w - xp.w};
    float xb[4] = {xp.x, xp.y, xp.z, xp.w};
    float fk[4] = {tk.x, tk.y, tk.z, tk.w};
    float fv[4] = {tv.x, tv.y, tv.z, tv.w};
    float fr[4] = {tr.x, tr.y, tr.z, tr.w};

    size_t gbase = (size_t)m * DD_ + (d & ~15);
#pragma unroll
    for (int e = 0; e < 4; e++) {
        int p = pos16((d & 15) + e);
        g_xk[gbase + p] = pack_split16(fmaf(fk[e], xd[e], xb[e]));
        g_xv[gbase + p] = pack_split16(fmaf(fv[e], xd[e], xb[e]));
        g_xr[gbase + p] = pack_split16(fmaf(fr[e], xd[e], xb[e]));
    }
}

// ---------------------------------------------------------------------------
// fp16 split GEMM core on mma.sync. 4-stage cp.async pipeline, ONE
// __syncthreads per chunk (write distance 2, 4 stages -> wrap-safe).
// TWO=1: D = (Ahi+Alo)*B (2 passes). TWO=0: D = Ahi*B (1 pass, r proj).
// ---------------------------------------------------------------------------
#define A_STAGE 16384
#define B_STAGE 8192
#define STAGE_BYTES (A_STAGE + B_STAGE)     // 24576
#define NSTAGE 4
#define NCHUNK (DD_ / 32)                   // 32
#define GEMM_SMEM (NSTAGE * STAGE_BYTES)    // 98304

__device__ __forceinline__ void issue_stage(unsigned stage_base,
                                            const unsigned* __restrict__ Ap,
                                            const __half* __restrict__ Bp,
                                            int m0, int n0, int k0u, int tid) {
#pragma unroll
    for (int i = 0; i < 8; i++) {            // A: 128 rows x 8 chunks(16B)
        int f = i * 128 + tid;
        int row = f >> 3, c = f & 7;
        unsigned dst = stage_base + row * 128 + ((c ^ ((row & 1) << 2)) << 4);
        cpasync16(dst, Ap + (size_t)(m0 + row) * DD_ + k0u + c * 4);
    }
#pragma unroll
    for (int i = 0; i < 4; i++) {            // B: 128 rows x 4 chunks(16B)
        int f = i * 128 + tid;
        int row = f >> 2, c = f & 3;
        unsigned dst = stage_base + A_STAGE + row * 64 + (((c + row) & 3) << 4);
        cpasync16(dst, Bp + (size_t)(n0 + row) * DD_ + k0u + c * 8);
    }
}

__device__ __forceinline__ void gemm_core(const unsigned* __restrict__ Ap,
                                          const __half* __restrict__ Bp,
                                          float* __restrict__ C,
                                          bool two, bool sig) {
    extern __shared__ __align__(128) char smem[];
    const unsigned sb = smem_u32(smem);
    const int tid = threadIdx.x;
    const int lane = tid & 31, warp = tid >> 5;
    const int g = lane >> 2, t = lane & 3;
    const int wm = (warp & 1) * 64;
    const int wn = (warp >> 1) * 64;
    const int m0 = blockIdx.y * 128, n0 = blockIdx.x * 128;
    const unsigned axor = (g & 1) << 2;

    float acc[4][8][4];
#pragma unroll
    for (int i = 0; i < 4; i++)
#pragma unroll
        for (int j = 0; j < 8; j++)
#pragma unroll
            for (int q = 0; q < 4; q++) acc[i][j][q] = 0.0f;

    issue_stage(sb, Ap, Bp, m0, n0, 0, tid);  CP_COMMIT();
    issue_stage(sb + STAGE_BYTES, Ap, Bp, m0, n0, 32, tid);  CP_COMMIT();

    for (int ch = 0; ch < NCHUNK; ch++) {
        CP_WAIT(1);
        __syncthreads();                     // single barrier per chunk
        if (ch + 2 < NCHUNK)
            issue_stage(sb + ((ch + 2) % NSTAGE) * STAGE_BYTES,
                        Ap, Bp, m0, n0, (ch + 2) * 32, tid);
        CP_COMMIT();

        const unsigned aT = sb + (ch % NSTAGE) * STAGE_BYTES;
        const unsigned bT = aT + A_STAGE;
#pragma unroll
        for (int s = 0; s < 2; s++) {
            const unsigned cA = (unsigned)(4 * s + t) ^ axor;
            const unsigned cBs = ((unsigned)(2 * s + (t >> 1) + g) & 3);
            const unsigned bOff = (cBs << 4) + ((t & 1) << 3);

            unsigned ah[4][4], al[4][4];
#pragma unroll
            for (int i = 0; i < 4; i++) {
                const int r0 = wm + i * 16 + g;
                uint4 q0 = lds128(aT + r0 * 128 + (cA << 4));
                uint4 q1 = lds128(aT + (r0 + 8) * 128 + (cA << 4));
                ah[i][0] = __byte_perm(q0.x, q0.y, 0x5410);
                ah[i][2] = __byte_perm(q0.z, q0.w, 0x5410);
                ah[i][1] = __byte_perm(q1.x, q1.y, 0x5410);
                ah[i][3] = __byte_perm(q1.z, q1.w, 0x5410);
                if (two) {
                    al[i][0] = __byte_perm(q0.x, q0.y, 0x7632);
                    al[i][2] = __byte_perm(q0.z, q0.w, 0x7632);
                    al[i][1] = __byte_perm(q1.x, q1.y, 0x7632);
                    al[i][3] = __byte_perm(q1.z, q1.w, 0x7632);
                }
            }
#pragma unroll
            for (int j = 0; j < 8; j++) {
                const int rb = wn + j * 8 + g;
                uint2 qb = lds64(bT + rb * 64 + bOff);
#pragma unroll
                for (int i = 0; i < 4; i++) {
                    mma16816h(acc[i][j], ah[i], qb.x, qb.y);
                    if (two) mma16816h(acc[i][j], al[i], qb.x, qb.y);
                }
            }
        }
    }

    // epilogue
#pragma unroll
    for (int i = 0; i < 4; i++) {
        const int row0 = m0 + wm + i * 16 + g;
#pragma unroll
        for (int j = 0; j < 8; j++) {
            const int col = n0 + wn + j * 8 + 2 * t;
            float2 lo = make_float2(acc[i][j][0], acc[i][j][1]);
            float2 hi = make_float2(acc[i][j][2], acc[i][j][3]);
            if (sig) {
                lo.x = sigmoidf_(lo.x); lo.y = sigmoidf_(lo.y);
                hi.x = sigmoidf_(hi.x); hi.y = sigmoidf_(hi.y);
            }
            *(float2*)(C + (size_t)row0 * DD_ + col) = lo;
            *(float2*)(C + (size_t)(row0 + 8) * DD_ + col) = hi;
        }
    }
}

// Fused projection GEMMs: blockIdx.z selects {k, v, r}
__global__ void __launch_bounds__(128, 2)
gemm_proj() {
    const int z = blockIdx.z;
    const unsigned* Ap = (z == 0) ? g_xk : (z == 1) ? g_xv : g_xr;
    const __half* Bp = g_wp + (size_t)z * DD_ * DD_;
    float* C = (z == 0) ? g_k : (z == 1) ? g_v : g_r;
    gemm_core(Ap, Bp, C, /*two=*/z < 2, /*sig=*/z == 2);
}

// Output GEMM: r*wkv (packed) x Wo -> out
__global__ void __launch_bounds__(128, 2)
gemm_out(float* __restrict__ out) {
    gemm_core(g_rw, g_wp + 3 * (size_t)DD_ * DD_, out, true, false);
}

// ---------------------------------------------------------------------------
// Parallel WKV scan: 8 segments of 256 steps (phase1 / combine / phase2)
// ---------------------------------------------------------------------------
__global__ void __launch_bounds__(128)
wkv_phase1(const float* __restrict__ tdv) {
    const int idx = blockIdx.x * 128 + threadIdx.x;
    const int c = idx & (BD_ - 1);
    const int seg = idx >> 13;
    const int b = c >> 10;
    const int d = c & (DD_ - 1);
    const float td = tdv[d];

    float aa = 0.f, bb = 0.f, pp = -1e30f;
    size_t base = ((size_t)b * TT_ + seg * SEGLEN) * DD_ + d;
    float kc[8], vc[8];
    for (int tb = 0; tb < SEGLEN; tb += 8) {
#pragma unroll
        for (int j = 0; j < 8; j++) {
            kc[j] = g_k[base + (size_t)j * DD_];
            vc[j] = g_v[base + (size_t)j * DD_];
        }
#pragma unroll
        for (int j = 0; j < 8; j++) {
            const float kt = kc[j], vt = vc[j];
            float ww2 = pp + td;
            float qq2 = fmaxf(ww2, kt);
            float e1b = __expf(ww2 - qq2);
            float e2b = __expf(kt - qq2);
            aa = fmaf(e1b, aa, e2b * vt);
            bb = fmaf(e1b, bb, e2b);
            pp = qq2;
        }
        base += (size_t)8 * DD_;
    }
    g_sa[seg][c] = aa; g_sb[seg][c] = bb; g_sp[seg][c] = pp;
}

__global__ void __launch_bounds__(128)
wkv_combine(const float* __restrict__ aa_in, const float* __restrict__ bb_in,
            const float* __restrict__ pp_in, const float* __restrict__ tdv,
            const float* __restrict__ x,
            float* __restrict__ outLast, float* __restrict__ outAA,
            float* __restrict__ outBB,  float* __restrict__ outPP) {
    const int c = blockIdx.x * 128 + threadIdx.x;
    const int b = c >> 10;
    const int d = c & (DD_ - 1);
    const float decay = (float)SEGLEN * tdv[d];

    float a = aa_in[c], bq = bb_in[c], p = pp_in[c];
#pragma unroll
    for (int s = 0; s < NSEG; s++) {
        g_ia[s][c] = a; g_ib[s][c] = bq; g_ip[s][c] = p;
        float pd = p + decay;
        float sp = g_sp[s][c];
        float pn = fmaxf(pd, sp);
        float e1 = __expf(pd - pn);
        float e2 = __expf(sp - pn);
        a  = fmaf(e1, a,  e2 * g_sa[s][c]);
        bq = fmaf(e1, bq, e2 * g_sb[s][c]);
        p = pn;
    }
    outAA[c] = a; outBB[c] = bq; outPP[c] = p;
    outLast[c] = x[((size_t)b * TT_ + TT_ - 1) * DD_ + d];
}

__global__ void __launch_bounds__(128)
wkv_phase2(const float* __restrict__ tfv, const float* __restrict__ tdv) {
    const int idx = blockIdx.x * 128 + threadIdx.x;
    const int c = idx & (BD_ - 1);
    const int seg = idx >> 13;
    const int b = c >> 10;
    const int d = c & (DD_ - 1);
    const float tf = tfv[d], td = tdv[d];

    float aa = g_ia[seg][c], bb = g_ib[seg][c], pp = g_ip[seg][c];
    size_t base = ((size_t)b * TT_ + seg * SEGLEN) * DD_ + d;
    const int dI = (d & ~15) | pos16(d & 15);
    size_t rwb = ((size_t)b * TT_ + seg * SEGLEN) * DD_ + dI;

    float kc[8], vc[8], rc[8];
    for (int tb = 0; tb < SEGLEN; tb += 8) {
#pragma unroll
        for (int j = 0; j < 8; j++) {
            kc[j] = g_k[base + (size_t)j * DD_];
            vc[j] = g_v[base + (size_t)j * DD_];
            rc[j] = g_r[base + (size_t)j * DD_];
        }
#pragma unroll
        for (int j = 0; j < 8; j++) {
            const float kt = kc[j], vt = vc[j];
            float ww = tf + kt;
            float qq = fmaxf(pp, ww);
            float e1 = __expf(pp - qq);
            float e2 = __expf(ww - qq);
            float wkv = fmaf(e1, aa, e2 * vt) / fmaf(e1, bb, e2);
            g_rw[rwb + (size_t)j * DD_] = pack_split16(rc[j] * wkv);

            float ww2 = pp + td;
            float qq2 = fmaxf(ww2, kt);
            float e1b = __expf(ww2 - qq2);
            float e2b = __expf(kt - qq2);
            aa = fmaf(e1b, aa, e2b * vt);
            bb = fmaf(e1b, bb, e2b);
            pp = qq2;
        }
        base += (size_t)8 * DD_;
        rwb  += (size_t)8 * DD_;
    }
}

// ---------------------------------------------------------------------------
// Launch. Inputs (metadata order): x, last_x, aa, bb, pp, time_mix_k,
//   time_mix_v, time_mix_r, time_first, time_decay, Wk, Wv, Wr, Wo
// Output: [out(M*D)] [lastx(B*D)] [aa] [bb] [pp]
// ---------------------------------------------------------------------------
extern "C" void kernel_launch(void* const* d_in, const int* in_sizes, int n_in,
                              void* d_out, int out_size) {
    const float* x     = (const float*)d_in[0];
    const float* lastx = (const float*)d_in[1];
    const float* aa    = (const float*)d_in[2];
    const float* bb    = (const float*)d_in[3];
    const float* pp    = (const float*)d_in[4];
    const float* tmk   = (const float*)d_in[5];
    const float* tmv   = (const float*)d_in[6];
    const float* tmr   = (const float*)d_in[7];
    const float* tf    = (const float*)d_in[8];
    const float* td    = (const float*)d_in[9];
    const float* Wk    = (const float*)d_in[10];
    const float* Wv    = (const float*)d_in[11];
    const float* Wr    = (const float*)d_in[12];
    const float* Wo    = (const float*)d_in[13];

    float* out = (float*)d_out;

    void* pdump;
    cudaGetSymbolAddress(&pdump, g_dump);

    cudaFuncSetAttribute(gemm_proj, cudaFuncAttributeMaxDynamicSharedMemorySize,
                         GEMM_SMEM);
    cudaFuncSetAttribute(gemm_out, cudaFuncAttributeMaxDynamicSharedMemorySize,
                         GEMM_SMEM);

    float* oLast = out + (size_t)MM_ * DD_;
    float* oAA   = oLast + BD_;
    float* oBB   = oAA + BD_;
    float* oPP   = oBB + BD_;
    if (out_size < MM_ * DD_ + 4 * BD_) {
        oLast = (float*)pdump;
        oAA = oLast + BD_; oBB = oAA + BD_; oPP = oBB + BD_;
    }

    prep_w<<<dim3(32, 32, 4), dim3(32, 32)>>>(Wk, Wv, Wr, Wo);
    prep_x<<<MM_ * DD_ / 4 / 256, 256>>>(x, lastx, tmk, tmv, tmr);

    dim3 pgrid(DD_ / 128, MM_ / 128, 3);   // (8, 128, 3) fused k/v/r
    gemm_proj<<<pgrid, 128, GEMM_SMEM>>>();

    wkv_phase1<<<NSEG * BD_ / 128, 128>>>(td);
    wkv_combine<<<BD_ / 128, 128>>>(aa, bb, pp, td, x, oLast, oAA, oBB, oPP);
    wkv_phase2<<<NSEG * BD_ / 128, 128>>>(tf, td);

    dim3 ogrid(DD_ / 128, MM_ / 128, 1);
    gemm_out<<<ogrid, 128, GEMM_SMEM>>>(out);
}

// round 13
// speedup vs baseline: 3.8739x; 1.0224x over previous
#include <cuda_runtime.h>
#include <cuda_fp16.h>
#include <cstdint>

// Problem constants (fixed by the dataset)
#define BB_   8
#define TT_   2048
#define DD_   1024
#define MM_   (BB_ * TT_)    // 16384
#define BD_   (BB_ * DD_)    // 8192
#define NSEG  8
#define SEGLEN (TT_ / NSEG)  // 256

// ---------------------------------------------------------------------------
// Scratch (__device__ globals; no cudaMalloc allowed)
//   Projection inputs: separate fp16 hi/lo planes (k-interleaved order).
//   g_rw: packed u32 (hi|lo<<16) fp16 split (k-interleaved) for the out-GEMM.
// ---------------------------------------------------------------------------
__device__ __half   g_xkh[MM_ * DD_], g_xkl[MM_ * DD_];
__device__ __half   g_xvh[MM_ * DD_], g_xvl[MM_ * DD_];
__device__ __half   g_xrh[MM_ * DD_];
__device__ unsigned g_rw[MM_ * DD_];
__device__ __half   g_wp[4 * DD_ * DD_];
__device__ float    g_k[MM_ * DD_];
__device__ float    g_v[MM_ * DD_];
__device__ float    g_r[MM_ * DD_];
// parallel-scan workspace
__device__ float g_sa[NSEG][BD_], g_sb[NSEG][BD_], g_sp[NSEG][BD_];
__device__ float g_ia[NSEG][BD_], g_ib[NSEG][BD_], g_ip[NSEG][BD_];
__device__ float g_dump[4 * BD_];

// ---------------------------------------------------------------------------
// Helpers
// ---------------------------------------------------------------------------
// k-interleave within a 16-group: word q holds (k2q,k2q+1) / (k2q+8,k2q+9)
__device__ __forceinline__ int pos16(int k) {
    return ((k & 6) << 1) | (k & 1) | (((k >> 3) & 1) << 1);
}
__device__ __forceinline__ unsigned smem_u32(const void* p) {
    unsigned a;
    asm("{ .reg .u64 t; cvta.to.shared.u64 t, %1; cvt.u32.u64 %0, t; }"
        : "=r"(a) : "l"(p));
    return a;
}
__device__ __forceinline__ unsigned pack_split16(float x) {
    __half h = __float2half_rn(x);
    float hf = __half2float(h);
    __half l = __float2half_rn(x - hf);
    return (unsigned)__half_as_ushort(h) | ((unsigned)__half_as_ushort(l) << 16);
}
__device__ __forceinline__ float sigmoidf_(float x) {
    return 1.0f / (1.0f + __expf(-x));
}
__device__ __forceinline__ void cpasync16(unsigned dst, const void* src) {
    asm volatile("cp.async.cg.shared.global [%0], [%1], 16;"
                 :: "r"(dst), "l"(src));
}
#define CP_COMMIT() asm volatile("cp.async.commit_group;")
#define CP_WAIT(N)  asm volatile("cp.async.wait_group %0;" :: "n"(N))

__device__ __forceinline__ uint4 lds128(unsigned a) {
    uint4 q;
    asm volatile("ld.shared.v4.u32 {%0,%1,%2,%3}, [%4];"
                 : "=r"(q.x), "=r"(q.y), "=r"(q.z), "=r"(q.w) : "r"(a));
    return q;
}
__device__ __forceinline__ uint2 lds64(unsigned a) {
    uint2 q;
    asm volatile("ld.shared.v2.u32 {%0,%1}, [%2];"
                 : "=r"(q.x), "=r"(q.y) : "r"(a));
    return q;
}

// mma.sync m16n8k16 row.col fp16 -> f32
__device__ __forceinline__ void mma16816h(float* d, const unsigned* a,
                                          unsigned b0, unsigned b1) {
    asm volatile(
        "mma.sync.aligned.m16n8k16.row.col.f32.f16.f16.f32 "
        "{%0,%1,%2,%3}, {%4,%5,%6,%7}, {%8,%9}, {%0,%1,%2,%3};"
        : "+f"(d[0]), "+f"(d[1]), "+f"(d[2]), "+f"(d[3])
        : "r"(a[0]), "r"(a[1]), "r"(a[2]), "r"(a[3]), "r"(b0), "r"(b1));
}

// ---------------------------------------------------------------------------
// prep_w: Wp[n*D + ilv(k)] = fp16(W[k*D + n])  (4 matrices, k-interleaved)
// ---------------------------------------------------------------------------
__global__ void prep_w(const float* __restrict__ w0, const float* __restrict__ w1,
                       const float* __restrict__ w2, const float* __restrict__ w3) {
    __shared__ float tile[32][33];
    const float* W = (blockIdx.z == 0) ? w0 : (blockIdx.z == 1) ? w1
                   : (blockIdx.z == 2) ? w2 : w3;
    __half* Out = g_wp + (size_t)blockIdx.z * DD_ * DD_;
    int k0 = blockIdx.y * 32, n0 = blockIdx.x * 32;
    tile[threadIdx.y][threadIdx.x] =
        W[(size_t)(k0 + threadIdx.y) * DD_ + n0 + threadIdx.x];
    __syncthreads();
    int kk = threadIdx.x;
    int dstk = k0 + (kk & 16) + pos16(kk & 15);
    Out[(size_t)(n0 + threadIdx.y) * DD_ + dstk] =
        __float2half_rn(tile[threadIdx.x][threadIdx.y]);
}

// ---------------------------------------------------------------------------
// prep_x: one thread per 16-elem d-group; vectorized interleaved plane stores
// ---------------------------------------------------------------------------
template <bool LO>
__device__ __forceinline__ void split_store(const float* v, __half* hp,
                                            __half* lp, size_t base) {
    unsigned short hr[16], lr[16];
#pragma unroll
    for (int e = 0; e < 16; e++) {
        __half h = __float2half_rn(v[e]);
        hr[e] = __half_as_ushort(h);
        if (LO) {
            __half l = __float2half_rn(v[e] - __half2float(h));
            lr[e] = __half_as_ushort(l);
        }
    }
    unsigned w[8];
#pragma unroll
    for (int j = 0; j < 4; j++) {
        w[2 * j]     = (unsigned)hr[2 * j]     | ((unsigned)hr[2 * j + 1] << 16);
        w[2 * j + 1] = (unsigned)hr[2 * j + 8] | ((unsigned)hr[2 * j + 9] << 16);
    }
    *(uint4*)(hp + base)     = make_uint4(w[0], w[1], w[2], w[3]);
    *(uint4*)(hp + base + 8) = make_uint4(w[4], w[5], w[6], w[7]);
    if (LO) {
#pragma unroll
        for (int j = 0; j < 4; j++) {
            w[2 * j]     = (unsigned)lr[2 * j]     | ((unsigned)lr[2 * j + 1] << 16);
            w[2 * j + 1] = (unsigned)lr[2 * j + 8] | ((unsigned)lr[2 * j + 9] << 16);
        }
        *(uint4*)(lp + base)     = make_uint4(w[0], w[1], w[2], w[3]);
        *(uint4*)(lp + base + 8) = make_uint4(w[4], w[5], w[6], w[7]);
    }
}

__global__ void __launch_bounds__(256)
prep_x(const float* __restrict__ x, const float* __restrict__ lastx,
       const float* __restrict__ tmk, const float* __restrict__ tmv,
       const float* __restrict__ tmr) {
    int mg = blockIdx.x * 256 + threadIdx.x;   // 16-element group index
    int m = mg >> 6;
    int d0 = (mg & 63) << 4;

    const float* xr = x + (size_t)m * DD_ + d0;
    const float* xpr = ((m & (TT_ - 1)) == 0)
                     ? lastx + (m >> 11) * DD_ + d0 : xr - DD_;

    float vx[16], vp[16], vd[16], vmix[16];
#pragma unroll
    for (int q = 0; q < 4; q++) {
        float4 a = *(const float4*)(xr + 4 * q);
        float4 b = *(const float4*)(xpr + 4 * q);
        vx[4 * q] = a.x; vx[4 * q + 1] = a.y; vx[4 * q + 2] = a.z; vx[4 * q + 3] = a.w;
        vp[4 * q] = b.x; vp[4 * q + 1] = b.y; vp[4 * q + 2] = b.z; vp[4 * q + 3] = b.w;
    }
#pragma unroll
    for (int e = 0; e < 16; e++) vd[e] = vx[e] - vp[e];

    size_t base = (size_t)m * DD_ + d0;
#pragma unroll
    for (int q = 0; q < 4; q++) {
        float4 tm = *(const float4*)(tmk + d0 + 4 * q);
        vmix[4 * q] = fmaf(tm.x, vd[4 * q], vp[4 * q]);
        vmix[4 * q + 1] = fmaf(tm.y, vd[4 * q + 1], vp[4 * q + 1]);
        vmix[4 * q + 2] = fmaf(tm.z, vd[4 * q + 2], vp[4 * q + 2]);
        vmix[4 * q + 3] = fmaf(tm.w, vd[4 * q + 3], vp[4 * q + 3]);
    }
    split_store<true>(vmix, g_xkh, g_xkl, base);
#pragma unroll
    for (int q = 0; q < 4; q++) {
        float4 tm = *(const float4*)(tmv + d0 + 4 * q);
        vmix[4 * q] = fmaf(tm.x, vd[4 * q], vp[4 * q]);
        vmix[4 * q + 1] = fmaf(tm.y, vd[4 * q + 1], vp[4 * q + 1]);
        vmix[4 * q + 2] = fmaf(tm.z, vd[4 * q + 2], vp[4 * q + 2]);
        vmix[4 * q + 3] = fmaf(tm.w, vd[4 * q + 3], vp[4 * q + 3]);
    }
    split_store<true>(vmix, g_xvh, g_xvl, base);
#pragma unroll
    for (int q = 0; q < 4; q++) {
        float4 tm = *(const float4*)(tmr + d0 + 4 * q);
        vmix[4 * q] = fmaf(tm.x, vd[4 * q], vp[4 * q]);
        vmix[4 * q + 1] = fmaf(tm.y, vd[4 * q + 1], vp[4 * q + 1]);
        vmix[4 * q + 2] = fmaf(tm.z, vd[4 * q + 2], vp[4 * q + 2]);
        vmix[4 * q + 3] = fmaf(tm.w, vd[4 * q + 3], vp[4 * q + 3]);
    }
    split_store<false>(vmix, g_xrh, nullptr, base);
}

// ---------------------------------------------------------------------------
// GEMM cores on mma.sync. CTA 128x128, 4 warps, BK=32, 4-stage cp.async,
// one __syncthreads per chunk.
//   Planes core: A as separate fp16 hi/lo planes — LDS.64 fragments, no PRMT.
//   Packed core: A as u32 (hi|lo<<16) — LDS.128 + PRMT (out-GEMM path).
// ---------------------------------------------------------------------------
#define AP_STAGE 8192                       // one A plane (128 x 32 x 2B)
#define B_STAGE  8192
#define STAGE_BYTES (2 * AP_STAGE + B_STAGE)   // 24576 (both cores)
#define NSTAGE 4
#define NCHUNK (DD_ / 32)                   // 32
#define GEMM_SMEM (NSTAGE * STAGE_BYTES)    // 98304

template <int NPASS>
__device__ __forceinline__ void issue_stage_pl(unsigned stage_base,
                                               const __half* __restrict__ Ah,
                                               const __half* __restrict__ Al,
                                               const __half* __restrict__ Bp,
                                               int m0, int n0, int k0u, int tid) {
#pragma unroll
    for (int i = 0; i < 4; i++) {            // A hi: 128 rows x 4 chunks(16B)
        int f = i * 128 + tid;
        int row = f >> 2, c = f & 3;
        unsigned dst = stage_base + row * 64 + ((c ^ (row & 3)) << 4);
        cpasync16(dst, Ah + (size_t)(m0 + row) * DD_ + k0u + c * 8);
    }
    if (NPASS == 2) {
#pragma unroll
        for (int i = 0; i < 4; i++) {        // A lo
            int f = i * 128 + tid;
            int row = f >> 2, c = f & 3;
            unsigned dst = stage_base + AP_STAGE + row * 64 + ((c ^ (row & 3)) << 4);
            cpasync16(dst, Al + (size_t)(m0 + row) * DD_ + k0u + c * 8);
        }
    }
#pragma unroll
    for (int i = 0; i < 4; i++) {            // B
        int f = i * 128 + tid;
        int row = f >> 2, c = f & 3;
        unsigned dst = stage_base + 2 * AP_STAGE + row * 64 + (((c + row) & 3) << 4);
        cpasync16(dst, Bp + (size_t)(n0 + row) * DD_ + k0u + c * 8);
    }
}

template <int NPASS, int SIG>
__device__ __forceinline__ void gemm_core_pl(const __half* __restrict__ Ah,
                                             const __half* __restrict__ Al,
                                             const __half* __restrict__ Bp,
                                             float* __restrict__ C) {
    extern __shared__ __align__(128) char smem[];
    const unsigned sb = smem_u32(smem);
    const int tid = threadIdx.x;
    const int lane = tid & 31, warp = tid >> 5;
    const int g = lane >> 2, t = lane & 3;
    const int wm = (warp & 1) * 64;
    const int wn = (warp >> 1) * 64;
    const int m0 = blockIdx.y * 128, n0 = blockIdx.x * 128;
    const unsigned tb8 = (t & 1) << 3;

    float acc[4][8][4];
#pragma unroll
    for (int i = 0; i < 4; i++)
#pragma unroll
        for (int j = 0; j < 8; j++)
#pragma unroll
            for (int q = 0; q < 4; q++) acc[i][j][q] = 0.0f;

    issue_stage_pl<NPASS>(sb, Ah, Al, Bp, m0, n0, 0, tid);  CP_COMMIT();
    issue_stage_pl<NPASS>(sb + STAGE_BYTES, Ah, Al, Bp, m0, n0, 32, tid);  CP_COMMIT();

    for (int ch = 0; ch < NCHUNK; ch++) {
        CP_WAIT(1);
        __syncthreads();
        if (ch + 2 < NCHUNK)
            issue_stage_pl<NPASS>(sb + ((ch + 2) % NSTAGE) * STAGE_BYTES,
                                  Ah, Al, Bp, m0, n0, (ch + 2) * 32, tid);
        CP_COMMIT();

        const unsigned aT = sb + (ch % NSTAGE) * STAGE_BYTES;
        const unsigned lT = aT + AP_STAGE;
        const unsigned bT = aT + 2 * AP_STAGE;
#pragma unroll
        for (int s = 0; s < 2; s++) {
            const int lc = 2 * s + (t >> 1);              // logical 16B chunk
            const unsigned aOff = ((unsigned)(lc ^ (g & 3)) << 4) + tb8;

            unsigned ah[4][4], al[4][4];
#pragma unroll
            for (int i = 0; i < 4; i++) {
                const int r0 = wm + i * 16 + g;
                uint2 q0 = lds64(aT + r0 * 64 + aOff);
                uint2 q1 = lds64(aT + (r0 + 8) * 64 + aOff);
                ah[i][0] = q0.x; ah[i][2] = q0.y;
                ah[i][1] = q1.x; ah[i][3] = q1.y;
                if (NPASS == 2) {
                    uint2 p0 = lds64(lT + r0 * 64 + aOff);
                    uint2 p1 = lds64(lT + (r0 + 8) * 64 + aOff);
                    al[i][0] = p0.x; al[i][2] = p0.y;
                    al[i][1] = p1.x; al[i][3] = p1.y;
                }
            }
#pragma unroll
            for (int j = 0; j < 8; j++) {
                const int rb = wn + j * 8 + g;
                uint2 qb = lds64(bT + rb * 64 + (((unsigned)((lc + g) & 3)) << 4) + tb8);
#pragma unroll
                for (int i = 0; i < 4; i++) {
                    mma16816h(acc[i][j], ah[i], qb.x, qb.y);
                    if (NPASS == 2) mma16816h(acc[i][j], al[i], qb.x, qb.y);
                }
            }
        }
    }

#pragma unroll
    for (int i = 0; i < 4; i++) {
        const int row0 = m0 + wm + i * 16 + g;
#pragma unroll
        for (int j = 0; j < 8; j++) {
            const int col = n0 + wn + j * 8 + 2 * t;
            float2 lo = make_float2(acc[i][j][0], acc[i][j][1]);
            float2 hi = make_float2(acc[i][j][2], acc[i][j][3]);
            if (SIG) {
                lo.x = sigmoidf_(lo.x); lo.y = sigmoidf_(lo.y);
                hi.x = sigmoidf_(hi.x); hi.y = sigmoidf_(hi.y);
            }
            *(float2*)(C + (size_t)row0 * DD_ + col) = lo;
            *(float2*)(C + (size_t)(row0 + 8) * DD_ + col) = hi;
        }
    }
}

// ---- packed-u32 core (out-GEMM): A = hi|lo<<16, 2 passes, PRMT unpack ----
__device__ __forceinline__ void issue_stage_pk(unsigned stage_base,
                                               const unsigned* __restrict__ Ap,
                                               const __half* __restrict__ Bp,
                                               int m0, int n0, int k0u, int tid) {
#pragma unroll
    for (int i = 0; i < 8; i++) {            // A: 128 rows x 8 chunks(16B)
        int f = i * 128 + tid;
        int row = f >> 3, c = f & 7;
        unsigned dst = stage_base + row * 128 + ((c ^ ((row & 1) << 2)) << 4);
        cpasync16(dst, Ap + (size_t)(m0 + row) * DD_ + k0u + c * 4);
    }
#pragma unroll
    for (int i = 0; i < 4; i++) {            // B
        int f = i * 128 + tid;
        int row = f >> 2, c = f & 3;
        unsigned dst = stage_base + 16384 + row * 64 + (((c + row) & 3) << 4);
        cpasync16(dst, Bp + (size_t)(n0 + row) * DD_ + k0u + c * 8);
    }
}

__device__ __forceinline__ void gemm_core_pk(const unsigned* __restrict__ Ap,
                                             const __half* __restrict__ Bp,
                                             float* __restrict__ C) {
    extern __shared__ __align__(128) char smem[];
    const unsigned sb = smem_u32(smem);
    const int tid = threadIdx.x;
    const int lane = tid & 31, warp = tid >> 5;
    const int g = lane >> 2, t = lane & 3;
    const int wm = (warp & 1) * 64;
    const int wn = (warp >> 1) * 64;
    const int m0 = blockIdx.y * 128, n0 = blockIdx.x * 128;
    const unsigned axor = (g & 1) << 2;

    float acc[4][8][4];
#pragma unroll
    for (int i = 0; i < 4; i++)
#pragma unroll
        for (int j = 0; j < 8; j++)
#pragma unroll
            for (int q = 0; q < 4; q++) acc[i][j][q] = 0.0f;

    issue_stage_pk(sb, Ap, Bp, m0, n0, 0, tid);  CP_COMMIT();
    issue_stage_pk(sb + STAGE_BYTES, Ap, Bp, m0, n0, 32, tid);  CP_COMMIT();

    for (int ch = 0; ch < NCHUNK; ch++) {
        CP_WAIT(1);
        __syncthreads();
        if (ch + 2 < NCHUNK)
            issue_stage_pk(sb + ((ch + 2) % NSTAGE) * STAGE_BYTES,
                           Ap, Bp, m0, n0, (ch + 2) * 32, tid);
        CP_COMMIT();

        const unsigned aT = sb + (ch % NSTAGE) * STAGE_BYTES;
        const unsigned bT = aT + 16384;
#pragma unroll
        for (int s = 0; s < 2; s++) {
            const unsigned cA = (unsigned)(4 * s + t) ^ axor;
            const unsigned cBs = ((unsigned)(2 * s + (t >> 1) + g) & 3);
            const unsigned bOff = (cBs << 4) + ((t & 1) << 3);

            unsigned ah[4][4], al[4][4];
#pragma unroll
            for (int i = 0; i < 4; i++) {
                const int r0 = wm + i * 16 + g;
                uint4 q0 = lds128(aT + r0 * 128 + (cA << 4));
                uint4 q1 = lds128(aT + (r0 + 8) * 128 + (cA << 4));
                ah[i][0] = __byte_perm(q0.x, q0.y, 0x5410);
                ah[i][2] = __byte_perm(q0.z, q0.w, 0x5410);
                ah[i][1] = __byte_perm(q1.x, q1.y, 0x5410);
                ah[i][3] = __byte_perm(q1.z, q1.w, 0x5410);
                al[i][0] = __byte_perm(q0.x, q0.y, 0x7632);
                al[i][2] = __byte_perm(q0.z, q0.w, 0x7632);
                al[i][1] = __byte_perm(q1.x, q1.y, 0x7632);
                al[i][3] = __byte_perm(q1.z, q1.w, 0x7632);
            }
#pragma unroll
            for (int j = 0; j < 8; j++) {
                const int rb = wn + j * 8 + g;
                uint2 qb = lds64(bT + rb * 64 + bOff);
#pragma unroll
                for (int i = 0; i < 4; i++) {
                    mma16816h(acc[i][j], ah[i], qb.x, qb.y);
                    mma16816h(acc[i][j], al[i], qb.x, qb.y);
                }
            }
        }
    }

#pragma unroll
    for (int i = 0; i < 4; i++) {
        const int row0 = m0 + wm + i * 16 + g;
#pragma unroll
        for (int j = 0; j < 8; j++) {
            const int col = n0 + wn + j * 8 + 2 * t;
            *(float2*)(C + (size_t)row0 * DD_ + col) =
                make_float2(acc[i][j][0], acc[i][j][1]);
            *(float2*)(C + (size_t)(row0 + 8) * DD_ + col) =
                make_float2(acc[i][j][2], acc[i][j][3]);
        }
    }
}

// Fused projection GEMMs: blockIdx.z selects {k, v, r} (compile-time bodies)
__global__ void __launch_bounds__(128, 2)
gemm_proj() {
    const int z = blockIdx.z;
    if (z == 0)
        gemm_core_pl<2, 0>(g_xkh, g_xkl, g_wp + 0 * (size_t)DD_ * DD_, g_k);
    else if (z == 1)
        gemm_core_pl<2, 0>(g_xvh, g_xvl, g_wp + 1 * (size_t)DD_ * DD_, g_v);
    else
        gemm_core_pl<1, 1>(g_xrh, nullptr, g_wp + 2 * (size_t)DD_ * DD_, g_r);
}

__global__ void __launch_bounds__(128, 2)
gemm_out(float* __restrict__ out) {
    gemm_core_pk(g_rw, g_wp + 3 * (size_t)DD_ * DD_, out);
}

// ---------------------------------------------------------------------------
// Parallel WKV scan: 8 segments of 256 steps (phase1 / combine / phase2)
// ---------------------------------------------------------------------------
__global__ void __launch_bounds__(128)
wkv_phase1(const float* __restrict__ tdv) {
    const int idx = blockIdx.x * 128 + threadIdx.x;
    const int c = idx & (BD_ - 1);
    const int seg = idx >> 13;
    const int b = c >> 10;
    const int d = c & (DD_ - 1);
    const float td = tdv[d];

    float aa = 0.f, bb = 0.f, pp = -1e30f;
    size_t base = ((size_t)b * TT_ + seg * SEGLEN) * DD_ + d;
    float kc[8], vc[8];
    for (int tb = 0; tb < SEGLEN; tb += 8) {
#pragma unroll
        for (int j = 0; j < 8; j++) {
            kc[j] = g_k[base + (size_t)j * DD_];
            vc[j] = g_v[base + (size_t)j * DD_];
        }
#pragma unroll
        for (int j = 0; j < 8; j++) {
            const float kt = kc[j], vt = vc[j];
            float ww2 = pp + td;
            float qq2 = fmaxf(ww2, kt);
            float e1b = __expf(ww2 - qq2);
            float e2b = __expf(kt - qq2);
            aa = fmaf(e1b, aa, e2b * vt);
            bb = fmaf(e1b, bb, e2b);
            pp = qq2;
        }
        base += (size_t)8 * DD_;
    }
    g_sa[seg][c] = aa; g_sb[seg][c] = bb; g_sp[seg][c] = pp;
}

__global__ void __launch_bounds__(128)
wkv_combine(const float* __restrict__ aa_in, const float* __restrict__ bb_in,
            const float* __restrict__ pp_in, const float* __restrict__ tdv,
            const float* __restrict__ x,
            float* __restrict__ outLast, float* __restrict__ outAA,
            float* __restrict__ outBB,  float* __restrict__ outPP) {
    const int c = blockIdx.x * 128 + threadIdx.x;
    const int b = c >> 10;
    const int d = c & (DD_ - 1);
    const float decay = (float)SEGLEN * tdv[d];

    float a = aa_in[c], bq = bb_in[c], p = pp_in[c];
#pragma unroll
    for (int s = 0; s < NSEG; s++) {
        g_ia[s][c] = a; g_ib[s][c] = bq; g_ip[s][c] = p;
        float pd = p + decay;
        float sp = g_sp[s][c];
        float pn = fmaxf(pd, sp);
        float e1 = __expf(pd - pn);
        float e2 = __expf(sp - pn);
        a  = fmaf(e1, a,  e2 * g_sa[s][c]);
        bq = fmaf(e1, bq, e2 * g_sb[s][c]);
        p = pn;
    }
    outAA[c] = a; outBB[c] = bq; outPP[c] = p;
    outLast[c] = x[((size_t)b * TT_ + TT_ - 1) * DD_ + d];
}

__global__ void __launch_bounds__(128)
wkv_phase2(const float* __restrict__ tfv, const float* __restrict__ tdv) {
    const int idx = blockIdx.x * 128 + threadIdx.x;
    const int c = idx & (BD_ - 1);
    const int seg = idx >> 13;
    const int b = c >> 10;
    const int d = c & (DD_ - 1);
    const float tf = tfv[d], td = tdv[d];

    float aa = g_ia[seg][c], bb = g_ib[seg][c], pp = g_ip[seg][c];
    size_t base = ((size_t)b * TT_ + seg * SEGLEN) * DD_ + d;
    const int dI = (d & ~15) | pos16(d & 15);
    size_t rwb = ((size_t)b * TT_ + seg * SEGLEN) * DD_ + dI;

    float kc[8], vc[8], rc[8];
    for (int tb = 0; tb < SEGLEN; tb += 8) {
#pragma unroll
        for (int j = 0; j < 8; j++) {
            kc[j] = g_k[base + (size_t)j * DD_];
            vc[j] = g_v[base + (size_t)j * DD_];
            rc[j] = g_r[base + (size_t)j * DD_];
        }
#pragma unroll
        for (int j = 0; j < 8; j++) {
            const float kt = kc[j], vt = vc[j];
            float ww = tf + kt;
            float qq = fmaxf(pp, ww);
            float e1 = __expf(pp - qq);
            float e2 = __expf(ww - qq);
            float wkv = fmaf(e1, aa, e2 * vt) / fmaf(e1, bb, e2);
            g_rw[rwb + (size_t)j * DD_] = pack_split16(rc[j] * wkv);

            float ww2 = pp + td;
            float qq2 = fmaxf(ww2, kt);
            float e1b = __expf(ww2 - qq2);
            float e2b = __expf(kt - qq2);
            aa = fmaf(e1b, aa, e2b * vt);
            bb = fmaf(e1b, bb, e2b);
            pp = qq2;
        }
        base += (size_t)8 * DD_;
        rwb  += (size_t)8 * DD_;
    }
}

// ---------------------------------------------------------------------------
// Launch. Inputs (metadata order): x, last_x, aa, bb, pp, time_mix_k,
//   time_mix_v, time_mix_r, time_first, time_decay, Wk, Wv, Wr, Wo
// Output: [out(M*D)] [lastx(B*D)] [aa] [bb] [pp]
// ---------------------------------------------------------------------------
extern "C" void kernel_launch(void* const* d_in, const int* in_sizes, int n_in,
                              void* d_out, int out_size) {
    const float* x     = (const float*)d_in[0];
    const float* lastx = (const float*)d_in[1];
    const float* aa    = (const float*)d_in[2];
    const float* bb    = (const float*)d_in[3];
    const float* pp    = (const float*)d_in[4];
    const float* tmk   = (const float*)d_in[5];
    const float* tmv   = (const float*)d_in[6];
    const float* tmr   = (const float*)d_in[7];
    const float* tf    = (const float*)d_in[8];
    const float* td    = (const float*)d_in[9];
    const float* Wk    = (const float*)d_in[10];
    const float* Wv    = (const float*)d_in[11];
    const float* Wr    = (const float*)d_in[12];
    const float* Wo    = (const float*)d_in[13];

    float* out = (float*)d_out;

    void* pdump;
    cudaGetSymbolAddress(&pdump, g_dump);

    cudaFuncSetAttribute(gemm_proj, cudaFuncAttributeMaxDynamicSharedMemorySize,
                         GEMM_SMEM);
    cudaFuncSetAttribute(gemm_out, cudaFuncAttributeMaxDynamicSharedMemorySize,
                         GEMM_SMEM);

    float* oLast = out + (size_t)MM_ * DD_;
    float* oAA   = oLast + BD_;
    float* oBB   = oAA + BD_;
    float* oPP   = oBB + BD_;
    if (out_size < MM_ * DD_ + 4 * BD_) {
        oLast = (float*)pdump;
        oAA = oLast + BD_; oBB = oAA + BD_; oPP = oBB + BD_;
    }

    prep_w<<<dim3(32, 32, 4), dim3(32, 32)>>>(Wk, Wv, Wr, Wo);
    prep_x<<<MM_ * DD_ / 16 / 256, 256>>>(x, lastx, tmk, tmv, tmr);

    dim3 pgrid(DD_ / 128, MM_ / 128, 3);   // (8, 128, 3) fused k/v/r
    gemm_proj<<<pgrid, 128, GEMM_SMEM>>>();

    wkv_phase1<<<NSEG * BD_ / 128, 128>>>(td);
    wkv_combine<<<BD_ / 128, 128>>>(aa, bb, pp, td, x, oLast, oAA, oBB, oPP);
    wkv_phase2<<<NSEG * BD_ / 128, 128>>>(tf, td);

    dim3 ogrid(DD_ / 128, MM_ / 128);
    gemm_out<<<ogrid, 128, GEMM_SMEM>>>(out);
}

// round 14
// speedup vs baseline: 4.7340x; 1.2220x over previous
#include <cuda_runtime.h>
#include <cuda_fp16.h>
#include <cstdint>

// Problem constants (fixed by the dataset)
#define BB_   8
#define TT_   2048
#define DD_   1024
#define MM_   (BB_ * TT_)    // 16384
#define BD_   (BB_ * DD_)    // 8192
#define NSEG  8
#define SEGLEN (TT_ / NSEG)  // 256

// ---------------------------------------------------------------------------
// Scratch (__device__ globals; no cudaMalloc allowed)
//   Projection inputs: single fp16 plane each (k-interleaved order).
//   g_rw: packed u32 (hi|lo<<16) fp16 split (k-interleaved) for the out-GEMM.
// ---------------------------------------------------------------------------
__device__ __half   g_xkh[MM_ * DD_];
__device__ __half   g_xvh[MM_ * DD_];
__device__ __half   g_xrh[MM_ * DD_];
__device__ unsigned g_rw[MM_ * DD_];
__device__ __half   g_wp[4 * DD_ * DD_];
__device__ float    g_k[MM_ * DD_];
__device__ float    g_v[MM_ * DD_];
__device__ float    g_r[MM_ * DD_];
// parallel-scan workspace
__device__ float g_sa[NSEG][BD_], g_sb[NSEG][BD_], g_sp[NSEG][BD_];
__device__ float g_ia[NSEG][BD_], g_ib[NSEG][BD_], g_ip[NSEG][BD_];
__device__ float g_dump[4 * BD_];

// ---------------------------------------------------------------------------
// Helpers
// ---------------------------------------------------------------------------
// k-interleave within a 16-group: word q holds (k2q,k2q+1) / (k2q+8,k2q+9)
__device__ __forceinline__ int pos16(int k) {
    return ((k & 6) << 1) | (k & 1) | (((k >> 3) & 1) << 1);
}
__device__ __forceinline__ unsigned smem_u32(const void* p) {
    unsigned a;
    asm("{ .reg .u64 t; cvta.to.shared.u64 t, %1; cvt.u32.u64 %0, t; }"
        : "=r"(a) : "l"(p));
    return a;
}
__device__ __forceinline__ unsigned pack_split16(float x) {
    __half h = __float2half_rn(x);
    float hf = __half2float(h);
    __half l = __float2half_rn(x - hf);
    return (unsigned)__half_as_ushort(h) | ((unsigned)__half_as_ushort(l) << 16);
}
__device__ __forceinline__ float sigmoidf_(float x) {
    return 1.0f / (1.0f + __expf(-x));
}
__device__ __forceinline__ void cpasync16(unsigned dst, const void* src) {
    asm volatile("cp.async.cg.shared.global [%0], [%1], 16;"
                 :: "r"(dst), "l"(src));
}
#define CP_COMMIT() asm volatile("cp.async.commit_group;")
#define CP_WAIT(N)  asm volatile("cp.async.wait_group %0;" :: "n"(N))

__device__ __forceinline__ uint4 lds128(unsigned a) {
    uint4 q;
    asm volatile("ld.shared.v4.u32 {%0,%1,%2,%3}, [%4];"
                 : "=r"(q.x), "=r"(q.y), "=r"(q.z), "=r"(q.w) : "r"(a));
    return q;
}
__device__ __forceinline__ uint2 lds64(unsigned a) {
    uint2 q;
    asm volatile("ld.shared.v2.u32 {%0,%1}, [%2];"
                 : "=r"(q.x), "=r"(q.y) : "r"(a));
    return q;
}

// mma.sync m16n8k16 row.col fp16 -> f32
__device__ __forceinline__ void mma16816h(float* d, const unsigned* a,
                                          unsigned b0, unsigned b1) {
    asm volatile(
        "mma.sync.aligned.m16n8k16.row.col.f32.f16.f16.f32 "
        "{%0,%1,%2,%3}, {%4,%5,%6,%7}, {%8,%9}, {%0,%1,%2,%3};"
        : "+f"(d[0]), "+f"(d[1]), "+f"(d[2]), "+f"(d[3])
        : "r"(a[0]), "r"(a[1]), "r"(a[2]), "r"(a[3]), "r"(b0), "r"(b1));
}

// ---------------------------------------------------------------------------
// prep_w: Wp[n*D + ilv(k)] = fp16(W[k*D + n])  (4 matrices, k-interleaved)
// ---------------------------------------------------------------------------
__global__ void prep_w(const float* __restrict__ w0, const float* __restrict__ w1,
                       const float* __restrict__ w2, const float* __restrict__ w3) {
    __shared__ float tile[32][33];
    const float* W = (blockIdx.z == 0) ? w0 : (blockIdx.z == 1) ? w1
                   : (blockIdx.z == 2) ? w2 : w3;
    __half* Out = g_wp + (size_t)blockIdx.z * DD_ * DD_;
    int k0 = blockIdx.y * 32, n0 = blockIdx.x * 32;
    tile[threadIdx.y][threadIdx.x] =
        W[(size_t)(k0 + threadIdx.y) * DD_ + n0 + threadIdx.x];
    __syncthreads();
    int kk = threadIdx.x;
    int dstk = k0 + (kk & 16) + pos16(kk & 15);
    Out[(size_t)(n0 + threadIdx.y) * DD_ + dstk] =
        __float2half_rn(tile[threadIdx.x][threadIdx.y]);
}

// ---------------------------------------------------------------------------
// prep_x: one thread per 16-elem d-group; fp16 planes (no lo), k-interleaved
// ---------------------------------------------------------------------------
__device__ __forceinline__ void h16_store(const float* v, __half* hp,
                                          size_t base) {
    unsigned short hr[16];
#pragma unroll
    for (int e = 0; e < 16; e++)
        hr[e] = __half_as_ushort(__float2half_rn(v[e]));
    unsigned w[8];
#pragma unroll
    for (int j = 0; j < 4; j++) {
        w[2 * j]     = (unsigned)hr[2 * j]     | ((unsigned)hr[2 * j + 1] << 16);
        w[2 * j + 1] = (unsigned)hr[2 * j + 8] | ((unsigned)hr[2 * j + 9] << 16);
    }
    *(uint4*)(hp + base)     = make_uint4(w[0], w[1], w[2], w[3]);
    *(uint4*)(hp + base + 8) = make_uint4(w[4], w[5], w[6], w[7]);
}

__global__ void __launch_bounds__(256)
prep_x(const float* __restrict__ x, const float* __restrict__ lastx,
       const float* __restrict__ tmk, const float* __restrict__ tmv,
       const float* __restrict__ tmr) {
    int mg = blockIdx.x * 256 + threadIdx.x;   // 16-element group index
    int m = mg >> 6;
    int d0 = (mg & 63) << 4;

    const float* xr = x + (size_t)m * DD_ + d0;
    const float* xpr = ((m & (TT_ - 1)) == 0)
                     ? lastx + (m >> 11) * DD_ + d0 : xr - DD_;

    float vx[16], vp[16], vd[16], vmix[16];
#pragma unroll
    for (int q = 0; q < 4; q++) {
        float4 a = *(const float4*)(xr + 4 * q);
        float4 b = *(const float4*)(xpr + 4 * q);
        vx[4 * q] = a.x; vx[4 * q + 1] = a.y; vx[4 * q + 2] = a.z; vx[4 * q + 3] = a.w;
        vp[4 * q] = b.x; vp[4 * q + 1] = b.y; vp[4 * q + 2] = b.z; vp[4 * q + 3] = b.w;
    }
#pragma unroll
    for (int e = 0; e < 16; e++) vd[e] = vx[e] - vp[e];

    size_t base = (size_t)m * DD_ + d0;
#pragma unroll
    for (int q = 0; q < 4; q++) {
        float4 tm = *(const float4*)(tmk + d0 + 4 * q);
        vmix[4 * q] = fmaf(tm.x, vd[4 * q], vp[4 * q]);
        vmix[4 * q + 1] = fmaf(tm.y, vd[4 * q + 1], vp[4 * q + 1]);
        vmix[4 * q + 2] = fmaf(tm.z, vd[4 * q + 2], vp[4 * q + 2]);
        vmix[4 * q + 3] = fmaf(tm.w, vd[4 * q + 3], vp[4 * q + 3]);
    }
    h16_store(vmix, g_xkh, base);
#pragma unroll
    for (int q = 0; q < 4; q++) {
        float4 tm = *(const float4*)(tmv + d0 + 4 * q);
        vmix[4 * q] = fmaf(tm.x, vd[4 * q], vp[4 * q]);
        vmix[4 * q + 1] = fmaf(tm.y, vd[4 * q + 1], vp[4 * q + 1]);
        vmix[4 * q + 2] = fmaf(tm.z, vd[4 * q + 2], vp[4 * q + 2]);
        vmix[4 * q + 3] = fmaf(tm.w, vd[4 * q + 3], vp[4 * q + 3]);
    }
    h16_store(vmix, g_xvh, base);
#pragma unroll
    for (int q = 0; q < 4; q++) {
        float4 tm = *(const float4*)(tmr + d0 + 4 * q);
        vmix[4 * q] = fmaf(tm.x, vd[4 * q], vp[4 * q]);
        vmix[4 * q + 1] = fmaf(tm.y, vd[4 * q + 1], vp[4 * q + 1]);
        vmix[4 * q + 2] = fmaf(tm.z, vd[4 * q + 2], vp[4 * q + 2]);
        vmix[4 * q + 3] = fmaf(tm.w, vd[4 * q + 3], vp[4 * q + 3]);
    }
    h16_store(vmix, g_xrh, base);
}

// ---------------------------------------------------------------------------
// GEMM cores on mma.sync. CTA 128x128, 4 warps, BK=32, 4-stage cp.async,
// one __syncthreads per chunk.
//   Planes core (projections): A = one fp16 plane, 1 MMA pass.
//   Packed core (out-GEMM): A = u32 (hi|lo<<16), 2 passes, PRMT unpack.
// ---------------------------------------------------------------------------
#define AP_STAGE 8192                       // one A plane (128 x 32 x 2B)
#define B_STAGE  8192
#define NSTAGE 4
#define NCHUNK (DD_ / 32)                   // 32
// projection (1-pass) stage: A + B = 16KB
#define PL_STAGE (AP_STAGE + B_STAGE)
#define PL_SMEM  (NSTAGE * PL_STAGE)        // 65536
// out (packed 2-pass) stage: A 16KB + B 8KB
#define PK_STAGE 24576
#define PK_SMEM  (NSTAGE * PK_STAGE)        // 98304

__device__ __forceinline__ void issue_stage_pl(unsigned stage_base,
                                               const __half* __restrict__ Ah,
                                               const __half* __restrict__ Bp,
                                               int m0, int n0, int k0u, int tid) {
#pragma unroll
    for (int i = 0; i < 4; i++) {            // A: 128 rows x 4 chunks(16B)
        int f = i * 128 + tid;
        int row = f >> 2, c = f & 3;
        unsigned dst = stage_base + row * 64 + ((c ^ (row & 3)) << 4);
        cpasync16(dst, Ah + (size_t)(m0 + row) * DD_ + k0u + c * 8);
    }
#pragma unroll
    for (int i = 0; i < 4; i++) {            // B
        int f = i * 128 + tid;
        int row = f >> 2, c = f & 3;
        unsigned dst = stage_base + AP_STAGE + row * 64 + (((c + row) & 3) << 4);
        cpasync16(dst, Bp + (size_t)(n0 + row) * DD_ + k0u + c * 8);
    }
}

template <int SIG>
__device__ __forceinline__ void gemm_core_pl(const __half* __restrict__ Ah,
                                             const __half* __restrict__ Bp,
                                             float* __restrict__ C) {
    extern __shared__ __align__(128) char smem[];
    const unsigned sb = smem_u32(smem);
    const int tid = threadIdx.x;
    const int lane = tid & 31, warp = tid >> 5;
    const int g = lane >> 2, t = lane & 3;
    const int wm = (warp & 1) * 64;
    const int wn = (warp >> 1) * 64;
    const int m0 = blockIdx.y * 128, n0 = blockIdx.x * 128;
    const unsigned tb8 = (t & 1) << 3;

    float acc[4][8][4];
#pragma unroll
    for (int i = 0; i < 4; i++)
#pragma unroll
        for (int j = 0; j < 8; j++)
#pragma unroll
            for (int q = 0; q < 4; q++) acc[i][j][q] = 0.0f;

    issue_stage_pl(sb, Ah, Bp, m0, n0, 0, tid);  CP_COMMIT();
    issue_stage_pl(sb + PL_STAGE, Ah, Bp, m0, n0, 32, tid);  CP_COMMIT();

    for (int ch = 0; ch < NCHUNK; ch++) {
        CP_WAIT(1);
        __syncthreads();
        if (ch + 2 < NCHUNK)
            issue_stage_pl(sb + ((ch + 2) % NSTAGE) * PL_STAGE,
                           Ah, Bp, m0, n0, (ch + 2) * 32, tid);
        CP_COMMIT();

        const unsigned aT = sb + (ch % NSTAGE) * PL_STAGE;
        const unsigned bT = aT + AP_STAGE;
#pragma unroll
        for (int s = 0; s < 2; s++) {
            const int lc = 2 * s + (t >> 1);              // logical 16B chunk
            const unsigned aOff = ((unsigned)(lc ^ (g & 3)) << 4) + tb8;

            unsigned ah[4][4];
#pragma unroll
            for (int i = 0; i < 4; i++) {
                const int r0 = wm + i * 16 + g;
                uint2 q0 = lds64(aT + r0 * 64 + aOff);
                uint2 q1 = lds64(aT + (r0 + 8) * 64 + aOff);
                ah[i][0] = q0.x; ah[i][2] = q0.y;
                ah[i][1] = q1.x; ah[i][3] = q1.y;
            }
#pragma unroll
            for (int j = 0; j < 8; j++) {
                const int rb = wn + j * 8 + g;
                uint2 qb = lds64(bT + rb * 64 + (((unsigned)((lc + g) & 3)) << 4) + tb8);
#pragma unroll
                for (int i = 0; i < 4; i++)
                    mma16816h(acc[i][j], ah[i], qb.x, qb.y);
            }
        }
    }

#pragma unroll
    for (int i = 0; i < 4; i++) {
        const int row0 = m0 + wm + i * 16 + g;
#pragma unroll
        for (int j = 0; j < 8; j++) {
            const int col = n0 + wn + j * 8 + 2 * t;
            float2 lo = make_float2(acc[i][j][0], acc[i][j][1]);
            float2 hi = make_float2(acc[i][j][2], acc[i][j][3]);
            if (SIG) {
                lo.x = sigmoidf_(lo.x); lo.y = sigmoidf_(lo.y);
                hi.x = sigmoidf_(hi.x); hi.y = sigmoidf_(hi.y);
            }
            *(float2*)(C + (size_t)row0 * DD_ + col) = lo;
            *(float2*)(C + (size_t)(row0 + 8) * DD_ + col) = hi;
        }
    }
}

// ---- packed-u32 core (out-GEMM): A = hi|lo<<16, 2 passes, PRMT unpack ----
__device__ __forceinline__ void issue_stage_pk(unsigned stage_base,
                                               const unsigned* __restrict__ Ap,
                                               const __half* __restrict__ Bp,
                                               int m0, int n0, int k0u, int tid) {
#pragma unroll
    for (int i = 0; i < 8; i++) {            // A: 128 rows x 8 chunks(16B)
        int f = i * 128 + tid;
        int row = f >> 3, c = f & 7;
        unsigned dst = stage_base + row * 128 + ((c ^ ((row & 1) << 2)) << 4);
        cpasync16(dst, Ap + (size_t)(m0 + row) * DD_ + k0u + c * 4);
    }
#pragma unroll
    for (int i = 0; i < 4; i++) {            // B
        int f = i * 128 + tid;
        int row = f >> 2, c = f & 3;
        unsigned dst = stage_base + 16384 + row * 64 + (((c + row) & 3) << 4);
        cpasync16(dst, Bp + (size_t)(n0 + row) * DD_ + k0u + c * 8);
    }
}

__device__ __forceinline__ void gemm_core_pk(const unsigned* __restrict__ Ap,
                                             const __half* __restrict__ Bp,
                                             float* __restrict__ C) {
    extern __shared__ __align__(128) char smem[];
    const unsigned sb = smem_u32(smem);
    const int tid = threadIdx.x;
    const int lane = tid & 31, warp = tid >> 5;
    const int g = lane >> 2, t = lane & 3;
    const int wm = (warp & 1) * 64;
    const int wn = (warp >> 1) * 64;
    const int m0 = blockIdx.y * 128, n0 = blockIdx.x * 128;
    const unsigned axor = (g & 1) << 2;

    float acc[4][8][4];
#pragma unroll
    for (int i = 0; i < 4; i++)
#pragma unroll
        for (int j = 0; j < 8; j++)
#pragma unroll
            for (int q = 0; q < 4; q++) acc[i][j][q] = 0.0f;

    issue_stage_pk(sb, Ap, Bp, m0, n0, 0, tid);  CP_COMMIT();
    issue_stage_pk(sb + PK_STAGE, Ap, Bp, m0, n0, 32, tid);  CP_COMMIT();

    for (int ch = 0; ch < NCHUNK; ch++) {
        CP_WAIT(1);
        __syncthreads();
        if (ch + 2 < NCHUNK)
            issue_stage_pk(sb + ((ch + 2) % NSTAGE) * PK_STAGE,
                           Ap, Bp, m0, n0, (ch + 2) * 32, tid);
        CP_COMMIT();

        const unsigned aT = sb + (ch % NSTAGE) * PK_STAGE;
        const unsigned bT = aT + 16384;
#pragma unroll
        for (int s = 0; s < 2; s++) {
            const unsigned cA = (unsigned)(4 * s + t) ^ axor;
            const unsigned cBs = ((unsigned)(2 * s + (t >> 1) + g) & 3);
            const unsigned bOff = (cBs << 4) + ((t & 1) << 3);

            unsigned ah[4][4], al[4][4];
#pragma unroll
            for (int i = 0; i < 4; i++) {
                const int r0 = wm + i * 16 + g;
                uint4 q0 = lds128(aT + r0 * 128 + (cA << 4));
                uint4 q1 = lds128(aT + (r0 + 8) * 128 + (cA << 4));
                ah[i][0] = __byte_perm(q0.x, q0.y, 0x5410);
                ah[i][2] = __byte_perm(q0.z, q0.w, 0x5410);
                ah[i][1] = __byte_perm(q1.x, q1.y, 0x5410);
                ah[i][3] = __byte_perm(q1.z, q1.w, 0x5410);
                al[i][0] = __byte_perm(q0.x, q0.y, 0x7632);
                al[i][2] = __byte_perm(q0.z, q0.w, 0x7632);
                al[i][1] = __byte_perm(q1.x, q1.y, 0x7632);
                al[i][3] = __byte_perm(q1.z, q1.w, 0x7632);
            }
#pragma unroll
            for (int j = 0; j < 8; j++) {
                const int rb = wn + j * 8 + g;
                uint2 qb = lds64(bT + rb * 64 + bOff);
#pragma unroll
                for (int i = 0; i < 4; i++) {
                    mma16816h(acc[i][j], ah[i], qb.x, qb.y);
                    mma16816h(acc[i][j], al[i], qb.x, qb.y);
                }
            }
        }
    }

#pragma unroll
    for (int i = 0; i < 4; i++) {
        const int row0 = m0 + wm + i * 16 + g;
#pragma unroll
        for (int j = 0; j < 8; j++) {
            const int col = n0 + wn + j * 8 + 2 * t;
            *(float2*)(C + (size_t)row0 * DD_ + col) =
                make_float2(acc[i][j][0], acc[i][j][1]);
            *(float2*)(C + (size_t)(row0 + 8) * DD_ + col) =
                make_float2(acc[i][j][2], acc[i][j][3]);
        }
    }
}

// Fused projection GEMMs: blockIdx.z selects {k, v, r}; all 1-pass fp16
__global__ void __launch_bounds__(128, 2)
gemm_proj() {
    const int z = blockIdx.z;
    if (z == 0)
        gemm_core_pl<0>(g_xkh, g_wp + 0 * (size_t)DD_ * DD_, g_k);
    else if (z == 1)
        gemm_core_pl<0>(g_xvh, g_wp + 1 * (size_t)DD_ * DD_, g_v);
    else
        gemm_core_pl<1>(g_xrh, g_wp + 2 * (size_t)DD_ * DD_, g_r);
}

__global__ void __launch_bounds__(128, 2)
gemm_out(float* __restrict__ out) {
    gemm_core_pk(g_rw, g_wp + 3 * (size_t)DD_ * DD_, out);
}

// ---------------------------------------------------------------------------
// Parallel WKV scan: 8 segments of 256 steps (phase1 / combine / phase2)
// ---------------------------------------------------------------------------
__global__ void __launch_bounds__(128)
wkv_phase1(const float* __restrict__ tdv) {
    const int idx = blockIdx.x * 128 + threadIdx.x;
    const int c = idx & (BD_ - 1);
    const int seg = idx >> 13;
    const int b = c >> 10;
    const int d = c & (DD_ - 1);
    const float td = tdv[d];

    float aa = 0.f, bb = 0.f, pp = -1e30f;
    size_t base = ((size_t)b * TT_ + seg * SEGLEN) * DD_ + d;
    float kc[8], vc[8];
    for (int tb = 0; tb < SEGLEN; tb += 8) {
#pragma unroll
        for (int j = 0; j < 8; j++) {
            kc[j] = g_k[base + (size_t)j * DD_];
            vc[j] = g_v[base + (size_t)j * DD_];
        }
#pragma unroll
        for (int j = 0; j < 8; j++) {
            const float kt = kc[j], vt = vc[j];
            float ww2 = pp + td;
            float qq2 = fmaxf(ww2, kt);
            float e1b = __expf(ww2 - qq2);
            float e2b = __expf(kt - qq2);
            aa = fmaf(e1b, aa, e2b * vt);
            bb = fmaf(e1b, bb, e2b);
            pp = qq2;
        }
        base += (size_t)8 * DD_;
    }
    g_sa[seg][c] = aa; g_sb[seg][c] = bb; g_sp[seg][c] = pp;
}

__global__ void __launch_bounds__(128)
wkv_combine(const float* __restrict__ aa_in, const float* __restrict__ bb_in,
            const float* __restrict__ pp_in, const float* __restrict__ tdv,
            const float* __restrict__ x,
            float* __restrict__ outLast, float* __restrict__ outAA,
            float* __restrict__ outBB,  float* __restrict__ outPP) {
    const int c = blockIdx.x * 128 + threadIdx.x;
    const int b = c >> 10;
    const int d = c & (DD_ - 1);
    const float decay = (float)SEGLEN * tdv[d];

    float a = aa_in[c], bq = bb_in[c], p = pp_in[c];
#pragma unroll
    for (int s = 0; s < NSEG; s++) {
        g_ia[s][c] = a; g_ib[s][c] = bq; g_ip[s][c] = p;
        float pd = p + decay;
        float sp = g_sp[s][c];
        float pn = fmaxf(pd, sp);
        float e1 = __expf(pd - pn);
        float e2 = __expf(sp - pn);
        a  = fmaf(e1, a,  e2 * g_sa[s][c]);
        bq = fmaf(e1, bq, e2 * g_sb[s][c]);
        p = pn;
    }
    outAA[c] = a; outBB[c] = bq; outPP[c] = p;
    outLast[c] = x[((size_t)b * TT_ + TT_ - 1) * DD_ + d];
}

__global__ void __launch_bounds__(128)
wkv_phase2(const float* __restrict__ tfv, const float* __restrict__ tdv) {
    const int idx = blockIdx.x * 128 + threadIdx.x;
    const int c = idx & (BD_ - 1);
    const int seg = idx >> 13;
    const int b = c >> 10;
    const int d = c & (DD_ - 1);
    const float tf = tfv[d], td = tdv[d];

    float aa = g_ia[seg][c], bb = g_ib[seg][c], pp = g_ip[seg][c];
    size_t base = ((size_t)b * TT_ + seg * SEGLEN) * DD_ + d;
    const int dI = (d & ~15) | pos16(d & 15);
    size_t rwb = ((size_t)b * TT_ + seg * SEGLEN) * DD_ + dI;

    float kc[8], vc[8], rc[8];
    for (int tb = 0; tb < SEGLEN; tb += 8) {
#pragma unroll
        for (int j = 0; j < 8; j++) {
            kc[j] = g_k[base + (size_t)j * DD_];
            vc[j] = g_v[base + (size_t)j * DD_];
            rc[j] = g_r[base + (size_t)j * DD_];
        }
#pragma unroll
        for (int j = 0; j < 8; j++) {
            const float kt = kc[j], vt = vc[j];
            float ww = tf + kt;
            float qq = fmaxf(pp, ww);
            float e1 = __expf(pp - qq);
            float e2 = __expf(ww - qq);
            float wkv = fmaf(e1, aa, e2 * vt) / fmaf(e1, bb, e2);
            g_rw[rwb + (size_t)j * DD_] = pack_split16(rc[j] * wkv);

            float ww2 = pp + td;
            float qq2 = fmaxf(ww2, kt);
            float e1b = __expf(ww2 - qq2);
            float e2b = __expf(kt - qq2);
            aa = fmaf(e1b, aa, e2b * vt);
            bb = fmaf(e1b, bb, e2b);
            pp = qq2;
        }
        base += (size_t)8 * DD_;
        rwb  += (size_t)8 * DD_;
    }
}

// ---------------------------------------------------------------------------
// Launch. Inputs (metadata order): x, last_x, aa, bb, pp, time_mix_k,
//   time_mix_v, time_mix_r, time_first, time_decay, Wk, Wv, Wr, Wo
// Output: [out(M*D)] [lastx(B*D)] [aa] [bb] [pp]
// ---------------------------------------------------------------------------
extern "C" void kernel_launch(void* const* d_in, const int* in_sizes, int n_in,
                              void* d_out, int out_size) {
    const float* x     = (const float*)d_in[0];
    const float* lastx = (const float*)d_in[1];
    const float* aa    = (const float*)d_in[2];
    const float* bb    = (const float*)d_in[3];
    const float* pp    = (const float*)d_in[4];
    const float* tmk   = (const float*)d_in[5];
    const float* tmv   = (const float*)d_in[6];
    const float* tmr   = (const float*)d_in[7];
    const float* tf    = (const float*)d_in[8];
    const float* td    = (const float*)d_in[9];
    const float* Wk    = (const float*)d_in[10];
    const float* Wv    = (const float*)d_in[11];
    const float* Wr    = (const float*)d_in[12];
    const float* Wo    = (const float*)d_in[13];

    float* out = (float*)d_out;

    void* pdump;
    cudaGetSymbolAddress(&pdump, g_dump);

    cudaFuncSetAttribute(gemm_proj, cudaFuncAttributeMaxDynamicSharedMemorySize,
                         PL_SMEM);
    cudaFuncSetAttribute(gemm_out, cudaFuncAttributeMaxDynamicSharedMemorySize,
                         PK_SMEM);

    float* oLast = out + (size_t)MM_ * DD_;
    float* oAA   = oLast + BD_;
    float* oBB   = oAA + BD_;
    float* oPP   = oBB + BD_;
    if (out_size < MM_ * DD_ + 4 * BD_) {
        oLast = (float*)pdump;
        oAA = oLast + BD_; oBB = oAA + BD_; oPP = oBB + BD_;
    }

    prep_w<<<dim3(32, 32, 4), dim3(32, 32)>>>(Wk, Wv, Wr, Wo);
    prep_x<<<MM_ * DD_ / 16 / 256, 256>>>(x, lastx, tmk, tmv, tmr);

    dim3 pgrid(DD_ / 128, MM_ / 128, 3);   // (8, 128, 3) fused k/v/r
    gemm_proj<<<pgrid, 128, PL_SMEM>>>();

    wkv_phase1<<<NSEG * BD_ / 128, 128>>>(td);
    wkv_combine<<<BD_ / 128, 128>>>(aa, bb, pp, td, x, oLast, oAA, oBB, oPP);
    wkv_phase2<<<NSEG * BD_ / 128, 128>>>(tf, td);

    dim3 ogrid(DD_ / 128, MM_ / 128);
    gemm_out<<<ogrid, 128, PK_SMEM>>>(out);
}

// round 15
// speedup vs baseline: 5.1051x; 1.0784x over previous
#include <cuda_runtime.h>
#include <cuda_fp16.h>
#include <cstdint>

// Problem constants (fixed by the dataset)
#define BB_   8
#define TT_   2048
#define DD_   1024
#define MM_   (BB_ * TT_)    // 16384
#define BD_   (BB_ * DD_)    // 8192
#define NSEG  8
#define SEGLEN (TT_ / NSEG)  // 256

// ---------------------------------------------------------------------------
// Scratch (__device__ globals; no cudaMalloc allowed)
//   All GEMM A-operands: single fp16 planes, k-interleaved order.
// ---------------------------------------------------------------------------
__device__ __half   g_xkh[MM_ * DD_];
__device__ __half   g_xvh[MM_ * DD_];
__device__ __half   g_xrh[MM_ * DD_];
__device__ __half   g_rwh[MM_ * DD_];
__device__ __half   g_wp[4 * DD_ * DD_];
__device__ float    g_k[MM_ * DD_];
__device__ float    g_v[MM_ * DD_];
__device__ float    g_r[MM_ * DD_];
// parallel-scan workspace
__device__ float g_sa[NSEG][BD_], g_sb[NSEG][BD_], g_sp[NSEG][BD_];
__device__ float g_ia[NSEG][BD_], g_ib[NSEG][BD_], g_ip[NSEG][BD_];
__device__ float g_dump[4 * BD_];

// ---------------------------------------------------------------------------
// Helpers
// ---------------------------------------------------------------------------
// k-interleave within a 16-group: word q holds (k2q,k2q+1) / (k2q+8,k2q+9)
__device__ __forceinline__ int pos16(int k) {
    return ((k & 6) << 1) | (k & 1) | (((k >> 3) & 1) << 1);
}
__device__ __forceinline__ unsigned smem_u32(const void* p) {
    unsigned a;
    asm("{ .reg .u64 t; cvta.to.shared.u64 t, %1; cvt.u32.u64 %0, t; }"
        : "=r"(a) : "l"(p));
    return a;
}
__device__ __forceinline__ float sigmoidf_(float x) {
    return 1.0f / (1.0f + __expf(-x));
}
__device__ __forceinline__ void cpasync16(unsigned dst, const void* src) {
    asm volatile("cp.async.cg.shared.global [%0], [%1], 16;"
                 :: "r"(dst), "l"(src));
}
#define CP_COMMIT() asm volatile("cp.async.commit_group;")
#define CP_WAIT(N)  asm volatile("cp.async.wait_group %0;" :: "n"(N))

__device__ __forceinline__ uint2 lds64(unsigned a) {
    uint2 q;
    asm volatile("ld.shared.v2.u32 {%0,%1}, [%2];"
                 : "=r"(q.x), "=r"(q.y) : "r"(a));
    return q;
}

// mma.sync m16n8k16 row.col fp16 -> f32
__device__ __forceinline__ void mma16816h(float* d, const unsigned* a,
                                          unsigned b0, unsigned b1) {
    asm volatile(
        "mma.sync.aligned.m16n8k16.row.col.f32.f16.f16.f32 "
        "{%0,%1,%2,%3}, {%4,%5,%6,%7}, {%8,%9}, {%0,%1,%2,%3};"
        : "+f"(d[0]), "+f"(d[1]), "+f"(d[2]), "+f"(d[3])
        : "r"(a[0]), "r"(a[1]), "r"(a[2]), "r"(a[3]), "r"(b0), "r"(b1));
}

// ---------------------------------------------------------------------------
// prep_w: Wp[n*D + ilv(k)] = fp16(W[k*D + n])  (4 matrices, k-interleaved)
// ---------------------------------------------------------------------------
__global__ void prep_w(const float* __restrict__ w0, const float* __restrict__ w1,
                       const float* __restrict__ w2, const float* __restrict__ w3) {
    __shared__ float tile[32][33];
    const float* W = (blockIdx.z == 0) ? w0 : (blockIdx.z == 1) ? w1
                   : (blockIdx.z == 2) ? w2 : w3;
    __half* Out = g_wp + (size_t)blockIdx.z * DD_ * DD_;
    int k0 = blockIdx.y * 32, n0 = blockIdx.x * 32;
    tile[threadIdx.y][threadIdx.x] =
        W[(size_t)(k0 + threadIdx.y) * DD_ + n0 + threadIdx.x];
    __syncthreads();
    int kk = threadIdx.x;
    int dstk = k0 + (kk & 16) + pos16(kk & 15);
    Out[(size_t)(n0 + threadIdx.y) * DD_ + dstk] =
        __float2half_rn(tile[threadIdx.x][threadIdx.y]);
}

// ---------------------------------------------------------------------------
// prep_x: one thread per 16-elem d-group; fp16 planes, k-interleaved
// ---------------------------------------------------------------------------
__device__ __forceinline__ void h16_store(const float* v, __half* hp,
                                          size_t base) {
    unsigned short hr[16];
#pragma unroll
    for (int e = 0; e < 16; e++)
        hr[e] = __half_as_ushort(__float2half_rn(v[e]));
    unsigned w[8];
#pragma unroll
    for (int j = 0; j < 4; j++) {
        w[2 * j]     = (unsigned)hr[2 * j]     | ((unsigned)hr[2 * j + 1] << 16);
        w[2 * j + 1] = (unsigned)hr[2 * j + 8] | ((unsigned)hr[2 * j + 9] << 16);
    }
    *(uint4*)(hp + base)     = make_uint4(w[0], w[1], w[2], w[3]);
    *(uint4*)(hp + base + 8) = make_uint4(w[4], w[5], w[6], w[7]);
}

__global__ void __launch_bounds__(256)
prep_x(const float* __restrict__ x, const float* __restrict__ lastx,
       const float* __restrict__ tmk, const float* __restrict__ tmv,
       const float* __restrict__ tmr) {
    int mg = blockIdx.x * 256 + threadIdx.x;   // 16-element group index
    int m = mg >> 6;
    int d0 = (mg & 63) << 4;

    const float* xr = x + (size_t)m * DD_ + d0;
    const float* xpr = ((m & (TT_ - 1)) == 0)
                     ? lastx + (m >> 11) * DD_ + d0 : xr - DD_;

    float vx[16], vp[16], vd[16], vmix[16];
#pragma unroll
    for (int q = 0; q < 4; q++) {
        float4 a = *(const float4*)(xr + 4 * q);
        float4 b = *(const float4*)(xpr + 4 * q);
        vx[4 * q] = a.x; vx[4 * q + 1] = a.y; vx[4 * q + 2] = a.z; vx[4 * q + 3] = a.w;
        vp[4 * q] = b.x; vp[4 * q + 1] = b.y; vp[4 * q + 2] = b.z; vp[4 * q + 3] = b.w;
    }
#pragma unroll
    for (int e = 0; e < 16; e++) vd[e] = vx[e] - vp[e];

    size_t base = (size_t)m * DD_ + d0;
#pragma unroll
    for (int q = 0; q < 4; q++) {
        float4 tm = *(const float4*)(tmk + d0 + 4 * q);
        vmix[4 * q] = fmaf(tm.x, vd[4 * q], vp[4 * q]);
        vmix[4 * q + 1] = fmaf(tm.y, vd[4 * q + 1], vp[4 * q + 1]);
        vmix[4 * q + 2] = fmaf(tm.z, vd[4 * q + 2], vp[4 * q + 2]);
        vmix[4 * q + 3] = fmaf(tm.w, vd[4 * q + 3], vp[4 * q + 3]);
    }
    h16_store(vmix, g_xkh, base);
#pragma unroll
    for (int q = 0; q < 4; q++) {
        float4 tm = *(const float4*)(tmv + d0 + 4 * q);
        vmix[4 * q] = fmaf(tm.x, vd[4 * q], vp[4 * q]);
        vmix[4 * q + 1] = fmaf(tm.y, vd[4 * q + 1], vp[4 * q + 1]);
        vmix[4 * q + 2] = fmaf(tm.z, vd[4 * q + 2], vp[4 * q + 2]);
        vmix[4 * q + 3] = fmaf(tm.w, vd[4 * q + 3], vp[4 * q + 3]);
    }
    h16_store(vmix, g_xvh, base);
#pragma unroll
    for (int q = 0; q < 4; q++) {
        float4 tm = *(const float4*)(tmr + d0 + 4 * q);
        vmix[4 * q] = fmaf(tm.x, vd[4 * q], vp[4 * q]);
        vmix[4 * q + 1] = fmaf(tm.y, vd[4 * q + 1], vp[4 * q + 1]);
        vmix[4 * q + 2] = fmaf(tm.z, vd[4 * q + 2], vp[4 * q + 2]);
        vmix[4 * q + 3] = fmaf(tm.w, vd[4 * q + 3], vp[4 * q + 3]);
    }
    h16_store(vmix, g_xrh, base);
}

// ---------------------------------------------------------------------------
// 1-pass fp16 GEMM core on mma.sync. CTA 128x128, 4 warps, BK=32,
// 4-stage cp.async, one __syncthreads per chunk.
// ---------------------------------------------------------------------------
#define AP_STAGE 8192                       // A plane (128 x 32 x 2B)
#define B_STAGE  8192
#define NSTAGE 4
#define NCHUNK (DD_ / 32)                   // 32
#define PL_STAGE (AP_STAGE + B_STAGE)       // 16384
#define PL_SMEM  (NSTAGE * PL_STAGE)        // 65536

__device__ __forceinline__ void issue_stage_pl(unsigned stage_base,
                                               const __half* __restrict__ Ah,
                                               const __half* __restrict__ Bp,
                                               int m0, int n0, int k0u, int tid) {
#pragma unroll
    for (int i = 0; i < 4; i++) {            // A: 128 rows x 4 chunks(16B)
        int f = i * 128 + tid;
        int row = f >> 2, c = f & 3;
        unsigned dst = stage_base + row * 64 + ((c ^ (row & 3)) << 4);
        cpasync16(dst, Ah + (size_t)(m0 + row) * DD_ + k0u + c * 8);
    }
#pragma unroll
    for (int i = 0; i < 4; i++) {            // B
        int f = i * 128 + tid;
        int row = f >> 2, c = f & 3;
        unsigned dst = stage_base + AP_STAGE + row * 64 + (((c + row) & 3) << 4);
        cpasync16(dst, Bp + (size_t)(n0 + row) * DD_ + k0u + c * 8);
    }
}

template <int SIG>
__device__ __forceinline__ void gemm_core_pl(const __half* __restrict__ Ah,
                                             const __half* __restrict__ Bp,
                                             float* __restrict__ C) {
    extern __shared__ __align__(128) char smem[];
    const unsigned sb = smem_u32(smem);
    const int tid = threadIdx.x;
    const int lane = tid & 31, warp = tid >> 5;
    const int g = lane >> 2, t = lane & 3;
    const int wm = (warp & 1) * 64;
    const int wn = (warp >> 1) * 64;
    const int m0 = blockIdx.y * 128, n0 = blockIdx.x * 128;
    const unsigned tb8 = (t & 1) << 3;

    float acc[4][8][4];
#pragma unroll
    for (int i = 0; i < 4; i++)
#pragma unroll
        for (int j = 0; j < 8; j++)
#pragma unroll
            for (int q = 0; q < 4; q++) acc[i][j][q] = 0.0f;

    issue_stage_pl(sb, Ah, Bp, m0, n0, 0, tid);  CP_COMMIT();
    issue_stage_pl(sb + PL_STAGE, Ah, Bp, m0, n0, 32, tid);  CP_COMMIT();

    for (int ch = 0; ch < NCHUNK; ch++) {
        CP_WAIT(1);
        __syncthreads();
        if (ch + 2 < NCHUNK)
            issue_stage_pl(sb + ((ch + 2) % NSTAGE) * PL_STAGE,
                           Ah, Bp, m0, n0, (ch + 2) * 32, tid);
        CP_COMMIT();

        const unsigned aT = sb + (ch % NSTAGE) * PL_STAGE;
        const unsigned bT = aT + AP_STAGE;
#pragma unroll
        for (int s = 0; s < 2; s++) {
            const int lc = 2 * s + (t >> 1);              // logical 16B chunk
            const unsigned aOff = ((unsigned)(lc ^ (g & 3)) << 4) + tb8;

            unsigned ah[4][4];
#pragma unroll
            for (int i = 0; i < 4; i++) {
                const int r0 = wm + i * 16 + g;
                uint2 q0 = lds64(aT + r0 * 64 + aOff);
                uint2 q1 = lds64(aT + (r0 + 8) * 64 + aOff);
                ah[i][0] = q0.x; ah[i][2] = q0.y;
                ah[i][1] = q1.x; ah[i][3] = q1.y;
            }
#pragma unroll
            for (int j = 0; j < 8; j++) {
                const int rb = wn + j * 8 + g;
                uint2 qb = lds64(bT + rb * 64 + (((unsigned)((lc + g) & 3)) << 4) + tb8);
#pragma unroll
                for (int i = 0; i < 4; i++)
                    mma16816h(acc[i][j], ah[i], qb.x, qb.y);
            }
        }
    }

#pragma unroll
    for (int i = 0; i < 4; i++) {
        const int row0 = m0 + wm + i * 16 + g;
#pragma unroll
        for (int j = 0; j < 8; j++) {
            const int col = n0 + wn + j * 8 + 2 * t;
            float2 lo = make_float2(acc[i][j][0], acc[i][j][1]);
            float2 hi = make_float2(acc[i][j][2], acc[i][j][3]);
            if (SIG) {
                lo.x = sigmoidf_(lo.x); lo.y = sigmoidf_(lo.y);
                hi.x = sigmoidf_(hi.x); hi.y = sigmoidf_(hi.y);
            }
            *(float2*)(C + (size_t)row0 * DD_ + col) = lo;
            *(float2*)(C + (size_t)(row0 + 8) * DD_ + col) = hi;
        }
    }
}

// Fused projection GEMMs: blockIdx.z selects {k, v, r}; all 1-pass fp16
__global__ void __launch_bounds__(128, 2)
gemm_proj() {
    const int z = blockIdx.z;
    if (z == 0)
        gemm_core_pl<0>(g_xkh, g_wp + 0 * (size_t)DD_ * DD_, g_k);
    else if (z == 1)
        gemm_core_pl<0>(g_xvh, g_wp + 1 * (size_t)DD_ * DD_, g_v);
    else
        gemm_core_pl<1>(g_xrh, g_wp + 2 * (size_t)DD_ * DD_, g_r);
}

// Output GEMM: r*wkv (fp16 plane) x Wo -> out  (1-pass)
__global__ void __launch_bounds__(128, 2)
gemm_out(float* __restrict__ out) {
    gemm_core_pl<0>(g_rwh, g_wp + 3 * (size_t)DD_ * DD_, out);
}

// ---------------------------------------------------------------------------
// Parallel WKV scan: 8 segments of 256 steps (phase1 / combine / phase2)
// ---------------------------------------------------------------------------
__global__ void __launch_bounds__(128)
wkv_phase1(const float* __restrict__ tdv) {
    const int idx = blockIdx.x * 128 + threadIdx.x;
    const int c = idx & (BD_ - 1);
    const int seg = idx >> 13;
    const int b = c >> 10;
    const int d = c & (DD_ - 1);
    const float td = tdv[d];

    float aa = 0.f, bb = 0.f, pp = -1e30f;
    size_t base = ((size_t)b * TT_ + seg * SEGLEN) * DD_ + d;
    float kc[8], vc[8];
    for (int tb = 0; tb < SEGLEN; tb += 8) {
#pragma unroll
        for (int j = 0; j < 8; j++) {
            kc[j] = g_k[base + (size_t)j * DD_];
            vc[j] = g_v[base + (size_t)j * DD_];
        }
#pragma unroll
        for (int j = 0; j < 8; j++) {
            const float kt = kc[j], vt = vc[j];
            float ww2 = pp + td;
            float qq2 = fmaxf(ww2, kt);
            float e1b = __expf(ww2 - qq2);
            float e2b = __expf(kt - qq2);
            aa = fmaf(e1b, aa, e2b * vt);
            bb = fmaf(e1b, bb, e2b);
            pp = qq2;
        }
        base += (size_t)8 * DD_;
    }
    g_sa[seg][c] = aa; g_sb[seg][c] = bb; g_sp[seg][c] = pp;
}

__global__ void __launch_bounds__(128)
wkv_combine(const float* __restrict__ aa_in, const float* __restrict__ bb_in,
            const float* __restrict__ pp_in, const float* __restrict__ tdv,
            const float* __restrict__ x,
            float* __restrict__ outLast, float* __restrict__ outAA,
            float* __restrict__ outBB,  float* __restrict__ outPP) {
    const int c = blockIdx.x * 128 + threadIdx.x;
    const int b = c >> 10;
    const int d = c & (DD_ - 1);
    const float decay = (float)SEGLEN * tdv[d];

    float a = aa_in[c], bq = bb_in[c], p = pp_in[c];
#pragma unroll
    for (int s = 0; s < NSEG; s++) {
        g_ia[s][c] = a; g_ib[s][c] = bq; g_ip[s][c] = p;
        float pd = p + decay;
        float sp = g_sp[s][c];
        float pn = fmaxf(pd, sp);
        float e1 = __expf(pd - pn);
        float e2 = __expf(sp - pn);
        a  = fmaf(e1, a,  e2 * g_sa[s][c]);
        bq = fmaf(e1, bq, e2 * g_sb[s][c]);
        p = pn;
    }
    outAA[c] = a; outBB[c] = bq; outPP[c] = p;
    outLast[c] = x[((size_t)b * TT_ + TT_ - 1) * DD_ + d];
}

__global__ void __launch_bounds__(128)
wkv_phase2(const float* __restrict__ tfv, const float* __restrict__ tdv) {
    const int idx = blockIdx.x * 128 + threadIdx.x;
    const int c = idx & (BD_ - 1);
    const int seg = idx >> 13;
    const int b = c >> 10;
    const int d = c & (DD_ - 1);
    const float tf = tfv[d], td = tdv[d];

    float aa = g_ia[seg][c], bb = g_ib[seg][c], pp = g_ip[seg][c];
    size_t base = ((size_t)b * TT_ + seg * SEGLEN) * DD_ + d;
    const int dI = (d & ~15) | pos16(d & 15);
    size_t rwb = ((size_t)b * TT_ + seg * SEGLEN) * DD_ + dI;

    float kc[8], vc[8], rc[8];
    for (int tb = 0; tb < SEGLEN; tb += 8) {
#pragma unroll
        for (int j = 0; j < 8; j++) {
            kc[j] = g_k[base + (size_t)j * DD_];
            vc[j] = g_v[base + (size_t)j * DD_];
            rc[j] = g_r[base + (size_t)j * DD_];
        }
#pragma unroll
        for (int j = 0; j < 8; j++) {
            const float kt = kc[j], vt = vc[j];
            float ww = tf + kt;
            float qq = fmaxf(pp, ww);
            float e1 = __expf(pp - qq);
            float e2 = __expf(ww - qq);
            float wkv = fmaf(e1, aa, e2 * vt) / fmaf(e1, bb, e2);
            g_rwh[rwb + (size_t)j * DD_] = __float2half_rn(rc[j] * wkv);

            float ww2 = pp + td;
            float qq2 = fmaxf(ww2, kt);
            float e1b = __expf(ww2 - qq2);
            float e2b = __expf(kt - qq2);
            aa = fmaf(e1b, aa, e2b * vt);
            bb = fmaf(e1b, bb, e2b);
            pp = qq2;
        }
        base += (size_t)8 * DD_;
        rwb  += (size_t)8 * DD_;
    }
}

// ---------------------------------------------------------------------------
// Launch. Inputs (metadata order): x, last_x, aa, bb, pp, time_mix_k,
//   time_mix_v, time_mix_r, time_first, time_decay, Wk, Wv, Wr, Wo
// Output: [out(M*D)] [lastx(B*D)] [aa] [bb] [pp]
// ---------------------------------------------------------------------------
extern "C" void kernel_launch(void* const* d_in, const int* in_sizes, int n_in,
                              void* d_out, int out_size) {
    const float* x     = (const float*)d_in[0];
    const float* lastx = (const float*)d_in[1];
    const float* aa    = (const float*)d_in[2];
    const float* bb    = (const float*)d_in[3];
    const float* pp    = (const float*)d_in[4];
    const float* tmk   = (const float*)d_in[5];
    const float* tmv   = (const float*)d_in[6];
    const float* tmr   = (const float*)d_in[7];
    const float* tf    = (const float*)d_in[8];
    const float* td    = (const float*)d_in[9];
    const float* Wk    = (const float*)d_in[10];
    const float* Wv    = (const float*)d_in[11];
    const float* Wr    = (const float*)d_in[12];
    const float* Wo    = (const float*)d_in[13];

    float* out = (float*)d_out;

    void* pdump;
    cudaGetSymbolAddress(&pdump, g_dump);

    cudaFuncSetAttribute(gemm_proj, cudaFuncAttributeMaxDynamicSharedMemorySize,
                         PL_SMEM);
    cudaFuncSetAttribute(gemm_out, cudaFuncAttributeMaxDynamicSharedMemorySize,
                         PL_SMEM);

    float* oLast = out + (size_t)MM_ * DD_;
    float* oAA   = oLast + BD_;
    float* oBB   = oAA + BD_;
    float* oPP   = oBB + BD_;
    if (out_size < MM_ * DD_ + 4 * BD_) {
        oLast = (float*)pdump;
        oAA = oLast + BD_; oBB = oAA + BD_; oPP = oBB + BD_;
    }

    prep_w<<<dim3(32, 32, 4), dim3(32, 32)>>>(Wk, Wv, Wr, Wo);
    prep_x<<<MM_ * DD_ / 16 / 256, 256>>>(x, lastx, tmk, tmv, tmr);

    dim3 pgrid(DD_ / 128, MM_ / 128, 3);   // (8, 128, 3) fused k/v/r
    gemm_proj<<<pgrid, 128, PL_SMEM>>>();

    wkv_phase1<<<NSEG * BD_ / 128, 128>>>(td);
    wkv_combine<<<BD_ / 128, 128>>>(aa, bb, pp, td, x, oLast, oAA, oBB, oPP);
    wkv_phase2<<<NSEG * BD_ / 128, 128>>>(tf, td);

    dim3 ogrid(DD_ / 128, MM_ / 128);
    gemm_out<<<ogrid, 128, PL_SMEM>>>(out);
}

// round 16
// speedup vs baseline: 5.2471x; 1.0278x over previous
#include <cuda_runtime.h>
#include <cuda_fp16.h>
#include <cstdint>

// Problem constants (fixed by the dataset)
#define BB_   8
#define TT_   2048
#define DD_   1024
#define MM_   (BB_ * TT_)    // 16384
#define BD_   (BB_ * DD_)    // 8192
#define NSEG  8
#define SEGLEN (TT_ / NSEG)  // 256

// ---------------------------------------------------------------------------
// Scratch (__device__ globals; no cudaMalloc allowed)
//   All GEMM A-operands: single fp16 planes, k-interleaved order.
// ---------------------------------------------------------------------------
__device__ __half   g_xkh[MM_ * DD_];
__device__ __half   g_xvh[MM_ * DD_];
__device__ __half   g_xrh[MM_ * DD_];
__device__ __half   g_rwh[MM_ * DD_];
__device__ __half   g_wp[4 * DD_ * DD_];
__device__ float    g_k[MM_ * DD_];
__device__ float    g_v[MM_ * DD_];
__device__ float    g_r[MM_ * DD_];
// parallel-scan workspace
__device__ float g_sa[NSEG][BD_], g_sb[NSEG][BD_], g_sp[NSEG][BD_];
__device__ float g_ia[NSEG][BD_], g_ib[NSEG][BD_], g_ip[NSEG][BD_];
__device__ float g_dump[4 * BD_];

// ---------------------------------------------------------------------------
// Helpers
// ---------------------------------------------------------------------------
// k-interleave within a 16-group: word q holds (k2q,k2q+1) / (k2q+8,k2q+9)
__device__ __forceinline__ int pos16(int k) {
    return ((k & 6) << 1) | (k & 1) | (((k >> 3) & 1) << 1);
}
__device__ __forceinline__ unsigned smem_u32(const void* p) {
    unsigned a;
    asm("{ .reg .u64 t; cvta.to.shared.u64 t, %1; cvt.u32.u64 %0, t; }"
        : "=r"(a) : "l"(p));
    return a;
}
__device__ __forceinline__ float sigmoidf_(float x) {
    return 1.0f / (1.0f + __expf(-x));
}
__device__ __forceinline__ void cpasync16(unsigned dst, const void* src) {
    asm volatile("cp.async.cg.shared.global [%0], [%1], 16;"
                 :: "r"(dst), "l"(src));
}
#define CP_COMMIT() asm volatile("cp.async.commit_group;")
#define CP_WAIT(N)  asm volatile("cp.async.wait_group %0;" :: "n"(N))

__device__ __forceinline__ uint2 lds64(unsigned a) {
    uint2 q;
    asm volatile("ld.shared.v2.u32 {%0,%1}, [%2];"
                 : "=r"(q.x), "=r"(q.y) : "r"(a));
    return q;
}

// mma.sync m16n8k16 row.col fp16 -> f32
__device__ __forceinline__ void mma16816h(float* d, const unsigned* a,
                                          unsigned b0, unsigned b1) {
    asm volatile(
        "mma.sync.aligned.m16n8k16.row.col.f32.f16.f16.f32 "
        "{%0,%1,%2,%3}, {%4,%5,%6,%7}, {%8,%9}, {%0,%1,%2,%3};"
        : "+f"(d[0]), "+f"(d[1]), "+f"(d[2]), "+f"(d[3])
        : "r"(a[0]), "r"(a[1]), "r"(a[2]), "r"(a[3]), "r"(b0), "r"(b1));
}

// ---------------------------------------------------------------------------
// prep_w: Wp[n*D + ilv(k)] = fp16(W[k*D + n])  (4 matrices, k-interleaved)
// ---------------------------------------------------------------------------
__global__ void prep_w(const float* __restrict__ w0, const float* __restrict__ w1,
                       const float* __restrict__ w2, const float* __restrict__ w3) {
    __shared__ float tile[32][33];
    const float* W = (blockIdx.z == 0) ? w0 : (blockIdx.z == 1) ? w1
                   : (blockIdx.z == 2) ? w2 : w3;
    __half* Out = g_wp + (size_t)blockIdx.z * DD_ * DD_;
    int k0 = blockIdx.y * 32, n0 = blockIdx.x * 32;
    tile[threadIdx.y][threadIdx.x] =
        W[(size_t)(k0 + threadIdx.y) * DD_ + n0 + threadIdx.x];
    __syncthreads();
    int kk = threadIdx.x;
    int dstk = k0 + (kk & 16) + pos16(kk & 15);
    Out[(size_t)(n0 + threadIdx.y) * DD_ + dstk] =
        __float2half_rn(tile[threadIdx.x][threadIdx.y]);
}

// ---------------------------------------------------------------------------
// prep_x: one thread per 16-elem d-group; fp16 planes, k-interleaved
// ---------------------------------------------------------------------------
__device__ __forceinline__ void h16_store(const float* v, __half* hp,
                                          size_t base) {
    unsigned short hr[16];
#pragma unroll
    for (int e = 0; e < 16; e++)
        hr[e] = __half_as_ushort(__float2half_rn(v[e]));
    unsigned w[8];
#pragma unroll
    for (int j = 0; j < 4; j++) {
        w[2 * j]     = (unsigned)hr[2 * j]     | ((unsigned)hr[2 * j + 1] << 16);
        w[2 * j + 1] = (unsigned)hr[2 * j + 8] | ((unsigned)hr[2 * j + 9] << 16);
    }
    *(uint4*)(hp + base)     = make_uint4(w[0], w[1], w[2], w[3]);
    *(uint4*)(hp + base + 8) = make_uint4(w[4], w[5], w[6], w[7]);
}

__global__ void __launch_bounds__(256)
prep_x(const float* __restrict__ x, const float* __restrict__ lastx,
       const float* __restrict__ tmk, const float* __restrict__ tmv,
       const float* __restrict__ tmr) {
    int mg = blockIdx.x * 256 + threadIdx.x;   // 16-element group index
    int m = mg >> 6;
    int d0 = (mg & 63) << 4;

    const float* xr = x + (size_t)m * DD_ + d0;
    const float* xpr = ((m & (TT_ - 1)) == 0)
                     ? lastx + (m >> 11) * DD_ + d0 : xr - DD_;

    float vx[16], vp[16], vd[16], vmix[16];
#pragma unroll
    for (int q = 0; q < 4; q++) {
        float4 a = *(const float4*)(xr + 4 * q);
        float4 b = *(const float4*)(xpr + 4 * q);
        vx[4 * q] = a.x; vx[4 * q + 1] = a.y; vx[4 * q + 2] = a.z; vx[4 * q + 3] = a.w;
        vp[4 * q] = b.x; vp[4 * q + 1] = b.y; vp[4 * q + 2] = b.z; vp[4 * q + 3] = b.w;
    }
#pragma unroll
    for (int e = 0; e < 16; e++) vd[e] = vx[e] - vp[e];

    size_t base = (size_t)m * DD_ + d0;
#pragma unroll
    for (int q = 0; q < 4; q++) {
        float4 tm = *(const float4*)(tmk + d0 + 4 * q);
        vmix[4 * q] = fmaf(tm.x, vd[4 * q], vp[4 * q]);
        vmix[4 * q + 1] = fmaf(tm.y, vd[4 * q + 1], vp[4 * q + 1]);
        vmix[4 * q + 2] = fmaf(tm.z, vd[4 * q + 2], vp[4 * q + 2]);
        vmix[4 * q + 3] = fmaf(tm.w, vd[4 * q + 3], vp[4 * q + 3]);
    }
    h16_store(vmix, g_xkh, base);
#pragma unroll
    for (int q = 0; q < 4; q++) {
        float4 tm = *(const float4*)(tmv + d0 + 4 * q);
        vmix[4 * q] = fmaf(tm.x, vd[4 * q], vp[4 * q]);
        vmix[4 * q + 1] = fmaf(tm.y, vd[4 * q + 1], vp[4 * q + 1]);
        vmix[4 * q + 2] = fmaf(tm.z, vd[4 * q + 2], vp[4 * q + 2]);
        vmix[4 * q + 3] = fmaf(tm.w, vd[4 * q + 3], vp[4 * q + 3]);
    }
    h16_store(vmix, g_xvh, base);
#pragma unroll
    for (int q = 0; q < 4; q++) {
        float4 tm = *(const float4*)(tmr + d0 + 4 * q);
        vmix[4 * q] = fmaf(tm.x, vd[4 * q], vp[4 * q]);
        vmix[4 * q + 1] = fmaf(tm.y, vd[4 * q + 1], vp[4 * q + 1]);
        vmix[4 * q + 2] = fmaf(tm.z, vd[4 * q + 2], vp[4 * q + 2]);
        vmix[4 * q + 3] = fmaf(tm.w, vd[4 * q + 3], vp[4 * q + 3]);
    }
    h16_store(vmix, g_xrh, base);
}

// ---------------------------------------------------------------------------
// 1-pass fp16 GEMM core on mma.sync. CTA 128x128, EIGHT warps (warp tile
// 64x32 -> 64 accum regs), BK=32, 4-stage cp.async, one barrier per chunk.
// __launch_bounds__(256,2) caps regs at 128 -> 2 CTAs/SM = 4 warps/SMSP.
// ---------------------------------------------------------------------------
#define AP_STAGE 8192                       // A plane (128 x 32 x 2B)
#define B_STAGE  8192
#define NSTAGE 4
#define NCHUNK (DD_ / 32)                   // 32
#define PL_STAGE (AP_STAGE + B_STAGE)       // 16384
#define PL_SMEM  (NSTAGE * PL_STAGE)        // 65536

__device__ __forceinline__ void issue_stage_pl(unsigned stage_base,
                                               const __half* __restrict__ Ah,
                                               const __half* __restrict__ Bp,
                                               int m0, int n0, int k0u, int tid) {
#pragma unroll
    for (int i = 0; i < 2; i++) {            // A: 128 rows x 4 chunks(16B)
        int f = i * 256 + tid;
        int row = f >> 2, c = f & 3;
        unsigned dst = stage_base + row * 64 + ((c ^ (row & 3)) << 4);
        cpasync16(dst, Ah + (size_t)(m0 + row) * DD_ + k0u + c * 8);
    }
#pragma unroll
    for (int i = 0; i < 2; i++) {            // B
        int f = i * 256 + tid;
        int row = f >> 2, c = f & 3;
        unsigned dst = stage_base + AP_STAGE + row * 64 + (((c + row) & 3) << 4);
        cpasync16(dst, Bp + (size_t)(n0 + row) * DD_ + k0u + c * 8);
    }
}

template <int SIG>
__device__ __forceinline__ void gemm_core_pl(const __half* __restrict__ Ah,
                                             const __half* __restrict__ Bp,
                                             float* __restrict__ C) {
    extern __shared__ __align__(128) char smem[];
    const unsigned sb = smem_u32(smem);
    const int tid = threadIdx.x;
    const int lane = tid & 31, warp = tid >> 5;   // warp 0..7
    const int g = lane >> 2, t = lane & 3;
    const int wm = (warp & 1) * 64;               // 2 warps over m
    const int wn = (warp >> 1) * 32;              // 4 warps over n
    const int m0 = blockIdx.y * 128, n0 = blockIdx.x * 128;
    const unsigned tb8 = (t & 1) << 3;

    float acc[4][4][4];
#pragma unroll
    for (int i = 0; i < 4; i++)
#pragma unroll
        for (int j = 0; j < 4; j++)
#pragma unroll
            for (int q = 0; q < 4; q++) acc[i][j][q] = 0.0f;

    issue_stage_pl(sb, Ah, Bp, m0, n0, 0, tid);  CP_COMMIT();
    issue_stage_pl(sb + PL_STAGE, Ah, Bp, m0, n0, 32, tid);  CP_COMMIT();

    for (int ch = 0; ch < NCHUNK; ch++) {
        CP_WAIT(1);
        __syncthreads();
        if (ch + 2 < NCHUNK)
            issue_stage_pl(sb + ((ch + 2) % NSTAGE) * PL_STAGE,
                           Ah, Bp, m0, n0, (ch + 2) * 32, tid);
        CP_COMMIT();

        const unsigned aT = sb + (ch % NSTAGE) * PL_STAGE;
        const unsigned bT = aT + AP_STAGE;
#pragma unroll
        for (int s = 0; s < 2; s++) {
            const int lc = 2 * s + (t >> 1);              // logical 16B chunk
            const unsigned aOff = ((unsigned)(lc ^ (g & 3)) << 4) + tb8;

            unsigned ah[4][4];
#pragma unroll
            for (int i = 0; i < 4; i++) {
                const int r0 = wm + i * 16 + g;
                uint2 q0 = lds64(aT + r0 * 64 + aOff);
                uint2 q1 = lds64(aT + (r0 + 8) * 64 + aOff);
                ah[i][0] = q0.x; ah[i][2] = q0.y;
                ah[i][1] = q1.x; ah[i][3] = q1.y;
            }
#pragma unroll
            for (int j = 0; j < 4; j++) {
                const int rb = wn + j * 8 + g;
                uint2 qb = lds64(bT + rb * 64 + (((unsigned)((lc + g) & 3)) << 4) + tb8);
#pragma unroll
                for (int i = 0; i < 4; i++)
                    mma16816h(acc[i][j], ah[i], qb.x, qb.y);
            }
        }
    }

#pragma unroll
    for (int i = 0; i < 4; i++) {
        const int row0 = m0 + wm + i * 16 + g;
#pragma unroll
        for (int j = 0; j < 4; j++) {
            const int col = n0 + wn + j * 8 + 2 * t;
            float2 lo = make_float2(acc[i][j][0], acc[i][j][1]);
            float2 hi = make_float2(acc[i][j][2], acc[i][j][3]);
            if (SIG) {
                lo.x = sigmoidf_(lo.x); lo.y = sigmoidf_(lo.y);
                hi.x = sigmoidf_(hi.x); hi.y = sigmoidf_(hi.y);
            }
            *(float2*)(C + (size_t)row0 * DD_ + col) = lo;
            *(float2*)(C + (size_t)(row0 + 8) * DD_ + col) = hi;
        }
    }
}

// Fused projection GEMMs: blockIdx.z selects {k, v, r}; all 1-pass fp16
__global__ void __launch_bounds__(256, 2)
gemm_proj() {
    const int z = blockIdx.z;
    if (z == 0)
        gemm_core_pl<0>(g_xkh, g_wp + 0 * (size_t)DD_ * DD_, g_k);
    else if (z == 1)
        gemm_core_pl<0>(g_xvh, g_wp + 1 * (size_t)DD_ * DD_, g_v);
    else
        gemm_core_pl<1>(g_xrh, g_wp + 2 * (size_t)DD_ * DD_, g_r);
}

// Output GEMM: r*wkv (fp16 plane) x Wo -> out  (1-pass)
__global__ void __launch_bounds__(256, 2)
gemm_out(float* __restrict__ out) {
    gemm_core_pl<0>(g_rwh, g_wp + 3 * (size_t)DD_ * DD_, out);
}

// ---------------------------------------------------------------------------
// Parallel WKV scan: 8 segments of 256 steps (phase1 / combine / phase2)
// ---------------------------------------------------------------------------
__global__ void __launch_bounds__(128)
wkv_phase1(const float* __restrict__ tdv) {
    const int idx = blockIdx.x * 128 + threadIdx.x;
    const int c = idx & (BD_ - 1);
    const int seg = idx >> 13;
    const int b = c >> 10;
    const int d = c & (DD_ - 1);
    const float td = tdv[d];

    float aa = 0.f, bb = 0.f, pp = -1e30f;
    size_t base = ((size_t)b * TT_ + seg * SEGLEN) * DD_ + d;
    float kc[8], vc[8];
    for (int tb = 0; tb < SEGLEN; tb += 8) {
#pragma unroll
        for (int j = 0; j < 8; j++) {
            kc[j] = g_k[base + (size_t)j * DD_];
            vc[j] = g_v[base + (size_t)j * DD_];
        }
#pragma unroll
        for (int j = 0; j < 8; j++) {
            const float kt = kc[j], vt = vc[j];
            float ww2 = pp + td;
            float qq2 = fmaxf(ww2, kt);
            float e1b = __expf(ww2 - qq2);
            float e2b = __expf(kt - qq2);
            aa = fmaf(e1b, aa, e2b * vt);
            bb = fmaf(e1b, bb, e2b);
            pp = qq2;
        }
        base += (size_t)8 * DD_;
    }
    g_sa[seg][c] = aa; g_sb[seg][c] = bb; g_sp[seg][c] = pp;
}

__global__ void __launch_bounds__(128)
wkv_combine(const float* __restrict__ aa_in, const float* __restrict__ bb_in,
            const float* __restrict__ pp_in, const float* __restrict__ tdv,
            const float* __restrict__ x,
            float* __restrict__ outLast, float* __restrict__ outAA,
            float* __restrict__ outBB,  float* __restrict__ outPP) {
    const int c = blockIdx.x * 128 + threadIdx.x;
    const int b = c >> 10;
    const int d = c & (DD_ - 1);
    const float decay = (float)SEGLEN * tdv[d];

    float a = aa_in[c], bq = bb_in[c], p = pp_in[c];
#pragma unroll
    for (int s = 0; s < NSEG; s++) {
        g_ia[s][c] = a; g_ib[s][c] = bq; g_ip[s][c] = p;
        float pd = p + decay;
        float sp = g_sp[s][c];
        float pn = fmaxf(pd, sp);
        float e1 = __expf(pd - pn);
        float e2 = __expf(sp - pn);
        a  = fmaf(e1, a,  e2 * g_sa[s][c]);
        bq = fmaf(e1, bq, e2 * g_sb[s][c]);
        p = pn;
    }
    outAA[c] = a; outBB[c] = bq; outPP[c] = p;
    outLast[c] = x[((size_t)b * TT_ + TT_ - 1) * DD_ + d];
}

__global__ void __launch_bounds__(128)
wkv_phase2(const float* __restrict__ tfv, const float* __restrict__ tdv) {
    const int idx = blockIdx.x * 128 + threadIdx.x;
    const int c = idx & (BD_ - 1);
    const int seg = idx >> 13;
    const int b = c >> 10;
    const int d = c & (DD_ - 1);
    const float tf = tfv[d], td = tdv[d];

    float aa = g_ia[seg][c], bb = g_ib[seg][c], pp = g_ip[seg][c];
    size_t base = ((size_t)b * TT_ + seg * SEGLEN) * DD_ + d;
    const int dI = (d & ~15) | pos16(d & 15);
    size_t rwb = ((size_t)b * TT_ + seg * SEGLEN) * DD_ + dI;

    float kc[8], vc[8], rc[8];
    for (int tb = 0; tb < SEGLEN; tb += 8) {
#pragma unroll
        for (int j = 0; j < 8; j++) {
            kc[j] = g_k[base + (size_t)j * DD_];
            vc[j] = g_v[base + (size_t)j * DD_];
            rc[j] = g_r[base + (size_t)j * DD_];
        }
#pragma unroll
        for (int j = 0; j < 8; j++) {
            const float kt = kc[j], vt = vc[j];
            float ww = tf + kt;
            float qq = fmaxf(pp, ww);
            float e1 = __expf(pp - qq);
            float e2 = __expf(ww - qq);
            float wkv = fmaf(e1, aa, e2 * vt) / fmaf(e1, bb, e2);
            g_rwh[rwb + (size_t)j * DD_] = __float2half_rn(rc[j] * wkv);

            float ww2 = pp + td;
            float qq2 = fmaxf(ww2, kt);
            float e1b = __expf(ww2 - qq2);
            float e2b = __expf(kt - qq2);
            aa = fmaf(e1b, aa, e2b * vt);
            bb = fmaf(e1b, bb, e2b);
            pp = qq2;
        }
        base += (size_t)8 * DD_;
        rwb  += (size_t)8 * DD_;
    }
}

// ---------------------------------------------------------------------------
// Launch. Inputs (metadata order): x, last_x, aa, bb, pp, time_mix_k,
//   time_mix_v, time_mix_r, time_first, time_decay, Wk, Wv, Wr, Wo
// Output: [out(M*D)] [lastx(B*D)] [aa] [bb] [pp]
// ---------------------------------------------------------------------------
extern "C" void kernel_launch(void* const* d_in, const int* in_sizes, int n_in,
                              void* d_out, int out_size) {
    const float* x     = (const float*)d_in[0];
    const float* lastx = (const float*)d_in[1];
    const float* aa    = (const float*)d_in[2];
    const float* bb    = (const float*)d_in[3];
    const float* pp    = (const float*)d_in[4];
    const float* tmk   = (const float*)d_in[5];
    const float* tmv   = (const float*)d_in[6];
    const float* tmr   = (const float*)d_in[7];
    const float* tf    = (const float*)d_in[8];
    const float* td    = (const float*)d_in[9];
    const float* Wk    = (const float*)d_in[10];
    const float* Wv    = (const float*)d_in[11];
    const float* Wr    = (const float*)d_in[12];
    const float* Wo    = (const float*)d_in[13];

    float* out = (float*)d_out;

    void* pdump;
    cudaGetSymbolAddress(&pdump, g_dump);

    cudaFuncSetAttribute(gemm_proj, cudaFuncAttributeMaxDynamicSharedMemorySize,
                         PL_SMEM);
    cudaFuncSetAttribute(gemm_out, cudaFuncAttributeMaxDynamicSharedMemorySize,
                         PL_SMEM);

    float* oLast = out + (size_t)MM_ * DD_;
    float* oAA   = oLast + BD_;
    float* oBB   = oAA + BD_;
    float* oPP   = oBB + BD_;
    if (out_size < MM_ * DD_ + 4 * BD_) {
        oLast = (float*)pdump;
        oAA = oLast + BD_; oBB = oAA + BD_; oPP = oBB + BD_;
    }

    prep_w<<<dim3(32, 32, 4), dim3(32, 32)>>>(Wk, Wv, Wr, Wo);
    prep_x<<<MM_ * DD_ / 16 / 256, 256>>>(x, lastx, tmk, tmv, tmr);

    dim3 pgrid(DD_ / 128, MM_ / 128, 3);   // (8, 128, 3) fused k/v/r
    gemm_proj<<<pgrid, 256, PL_SMEM>>>();

    wkv_phase1<<<NSEG * BD_ / 128, 128>>>(td);
    wkv_combine<<<BD_ / 128, 128>>>(aa, bb, pp, td, x, oLast, oAA, oBB, oPP);
    wkv_phase2<<<NSEG * BD_ / 128, 128>>>(tf, td);

    dim3 ogrid(DD_ / 128, MM_ / 128);
    gemm_out<<<ogrid, 256, PL_SMEM>>>(out);
}